// round 13
// baseline (speedup 1.0000x reference)
#include <cuda_runtime.h>
#include <cuda_bf16.h>
#include <math.h>
#include <stdint.h>

#define N_USER 60000
#define N_ITEM 40000
#define NN     100000
#define D      64
#define NNZ    1600000
#define BB     16384
#define NLAYERS 2
#define NB     98          // ceil(NN/1024)

typedef unsigned long long u64;

// ---------------- packed f32x2 helpers ----------------
__device__ __forceinline__ u64 f2dup(float v) {
    u64 r; asm("mov.b64 %0,{%1,%1};" : "=l"(r) : "f"(v)); return r;
}
__device__ __forceinline__ u64 ffma2(u64 a, u64 b, u64 c) {
    u64 d; asm("fma.rn.f32x2 %0,%1,%2,%3;" : "=l"(d) : "l"(a), "l"(b), "l"(c)); return d;
}
__device__ __forceinline__ u64 fmul2(u64 a, u64 b) {
    u64 d; asm("mul.rn.f32x2 %0,%1,%2;" : "=l"(d) : "l"(a), "l"(b)); return d;
}
__device__ __forceinline__ u64 fadd2(u64 a, u64 b) {
    u64 d; asm("add.rn.f32x2 %0,%1,%2;" : "=l"(d) : "l"(a), "l"(b)); return d;
}
__device__ __forceinline__ void funpack2(u64 v, float& lo, float& hi) {
    asm("mov.b64 {%0,%1},%2;" : "=f"(lo), "=f"(hi) : "l"(v));
}

// ---------------- mma.sync helpers ----------------
__device__ __forceinline__ uint32_t smem_to_u32(const void* p) {
    uint32_t a;
    asm("{ .reg .u64 t; cvta.to.shared.u64 t, %1; cvt.u32.u64 %0, t; }" : "=r"(a) : "l"(p));
    return a;
}
__device__ __forceinline__ void ldsm4(uint32_t* r, uint32_t addr) {
    asm volatile("ldmatrix.sync.aligned.m8n8.x4.shared.b16 {%0,%1,%2,%3}, [%4];"
        : "=r"(r[0]), "=r"(r[1]), "=r"(r[2]), "=r"(r[3]) : "r"(addr));
}
__device__ __forceinline__ uint32_t lds32(uint32_t addr) {
    uint32_t v; asm volatile("ld.shared.b32 %0, [%1];" : "=r"(v) : "r"(addr)); return v;
}
__device__ __forceinline__ void mma16816(float* d, const uint32_t* a, const uint32_t* b) {
    asm volatile(
        "mma.sync.aligned.m16n8k16.row.col.f32.bf16.bf16.f32 "
        "{%0,%1,%2,%3}, {%4,%5,%6,%7}, {%8,%9}, {%0,%1,%2,%3};"
        : "+f"(d[0]), "+f"(d[1]), "+f"(d[2]), "+f"(d[3])
        : "r"(a[0]), "r"(a[1]), "r"(a[2]), "r"(a[3]), "r"(b[0]), "r"(b[1]));
}

__device__ __forceinline__ void split2(float a, float b, uint32_t& hi, uint32_t& lo) {
    __nv_bfloat16 ah = __float2bfloat16(a);
    __nv_bfloat16 bh = __float2bfloat16(b);
    __nv_bfloat16 al = __float2bfloat16(a - __bfloat162float(ah));
    __nv_bfloat16 bl = __float2bfloat16(b - __bfloat162float(bh));
    hi = (uint32_t)__bfloat16_as_ushort(ah) | ((uint32_t)__bfloat16_as_ushort(bh) << 16);
    lo = (uint32_t)__bfloat16_as_ushort(al) | ((uint32_t)__bfloat16_as_ushort(bl) << 16);
}

#define STRD 72
#define STRDW 36

// ---------------- scratch ----------------
__device__ float    g_X[NN * D];
__device__ float    g_facc[NN * D];
__device__ float    g_h12[3][NN * D];
__device__ uint32_t g_Ah[3][NN * 32];
__device__ uint32_t g_Al[3][NN * 32];
__device__ uint32_t g_A2h[3][NN * 32];
__device__ uint32_t g_A2l[3][NN * 32];
__device__ int   g_rowptr[3][NN + 1];   // block-LOCAL exclusive scans (+blk at use)
__device__ u64   g_edge[3][NNZ];
__device__ int   g_count3[3][NN];       // zero-init; scan_local re-zeroes after read
__device__ int   g_cursor3[3][NN];      // block-local cursors
__device__ int   g_blk[3][128];         // per-block exclusive offsets
__device__ float g_attsum[NLAYERS][3];
__device__ uint4 g_Wpack[NLAYERS][10][576];

// ---------------- setup: zero attsums, init X ----------------
__global__ void setup_kernel(const float* __restrict__ uE, const float* __restrict__ iE) {
    int i = blockIdx.x * blockDim.x + threadIdx.x;
    if (i < NLAYERS * 3) ((float*)g_attsum)[i] = 0.f;
    if (i < NN * D / 4) {
        int j = i * 4;
        float4 v = (j < N_USER * D) ? ((const float4*)uE)[i]
                                    : ((const float4*)iE)[i - N_USER * D / 4];
        ((float4*)g_X)[i] = v;
    }
}

// ---------------- weight pre-conversion (once per launch) ----------------
__global__ void wconv_kernel(const float* __restrict__ linW, const float* __restrict__ intW,
                             const float* __restrict__ aW0, const float* __restrict__ aW1,
                             const float* __restrict__ aW2) {
    int l = blockIdx.x, m = blockIdx.y;
    const float* src = (m == 0) ? linW : (m == 1) ? intW
                      : (m == 2) ? aW0 : (m == 3) ? aW1 : aW2;
    src += l * 4096;
    unsigned short* dh = (unsigned short*)&g_Wpack[l][m * 2][0];
    unsigned short* dl = (unsigned short*)&g_Wpack[l][m * 2 + 1][0];
    for (int i = threadIdx.x; i < 4096; i += 256) {
        int k = i >> 6, n = i & 63;
        float w = src[i];
        __nv_bfloat16 h = __float2bfloat16(w);
        dh[n * STRD + k] = __bfloat16_as_ushort(h);
        dl[n * STRD + k] = __bfloat16_as_ushort(__float2bfloat16(w - __bfloat162float(h)));
    }
}

// ---------------- CSR build (per-relation) ----------------
__global__ void hist_kernel(const int* __restrict__ row, int r) {
    int e4 = blockIdx.x * blockDim.x + threadIdx.x;
    if (e4 < NNZ / 4) {
        int4 rr = ((const int4*)row)[e4];
        atomicAdd(&g_count3[r][rr.x], 1);
        atomicAdd(&g_count3[r][rr.y], 1);
        atomicAdd(&g_count3[r][rr.z], 1);
        atomicAdd(&g_count3[r][rr.w], 1);
    }
}

__global__ void scan_local_kernel(int r) {
    __shared__ int s[1024];
    int i = blockIdx.x * 1024 + threadIdx.x;
    int c = 0;
    if (i < NN) {
        c = g_count3[r][i];
        g_count3[r][i] = 0;            // reset for next graph replay
    }
    s[threadIdx.x] = c;
    __syncthreads();
    for (int off = 1; off < 1024; off <<= 1) {
        int t = (threadIdx.x >= off) ? s[threadIdx.x - off] : 0;
        __syncthreads();
        s[threadIdx.x] += t;
        __syncthreads();
    }
    if (i < NN) {
        int excl = s[threadIdx.x] - c;
        g_rowptr[r][i]  = excl;
        g_cursor3[r][i] = excl;
    }
    if (threadIdx.x == 1023) g_blk[r][blockIdx.x] = s[1023];
}

__global__ void scan_blk_kernel(int r) {
    __shared__ int s[128];
    int tid = threadIdx.x;
    int v = (tid < NB) ? g_blk[r][tid] : 0;
    s[tid] = v;
    __syncthreads();
    for (int off = 1; off < 128; off <<= 1) {
        int t = (tid >= off) ? s[tid - off] : 0;
        __syncthreads();
        s[tid] += t;
        __syncthreads();
    }
    if (tid < NB) g_blk[r][tid] = s[tid] - v;
    if (tid == NB - 1) g_rowptr[r][NN] = v;
}

// 8 edges/thread for deeper atomic pipelining
__global__ void scatter_kernel(const int* __restrict__ row, const int* __restrict__ col,
                               const float* __restrict__ val, int r) {
    int e8 = blockIdx.x * blockDim.x + threadIdx.x;
    if (e8 < NNZ / 8) {
        u64* __restrict__ ed = g_edge[r];
        const int* __restrict__ blk = g_blk[r];
        #pragma unroll
        for (int h = 0; h < 2; h++) {
            int e4 = e8 * 2 + h;
            int4   rr = ((const int4*)row)[e4];
            int4   cc = ((const int4*)col)[e4];
            float4 vv = ((const float4*)val)[e4];
            int p;
            p = atomicAdd(&g_cursor3[r][rr.x], 1) + blk[rr.x >> 10];
            ed[p] = ((u64)(uint32_t)__float_as_int(vv.x) << 32) | (uint32_t)cc.x;
            p = atomicAdd(&g_cursor3[r][rr.y], 1) + blk[rr.y >> 10];
            ed[p] = ((u64)(uint32_t)__float_as_int(vv.y) << 32) | (uint32_t)cc.y;
            p = atomicAdd(&g_cursor3[r][rr.z], 1) + blk[rr.z >> 10];
            ed[p] = ((u64)(uint32_t)__float_as_int(vv.z) << 32) | (uint32_t)cc.z;
            p = atomicAdd(&g_cursor3[r][rr.w], 1) + blk[rr.w >> 10];
            ed[p] = ((u64)(uint32_t)__float_as_int(vv.w) << 32) | (uint32_t)cc.w;
        }
    }
}

// fused SpMM: A = L@X + X, A2 = L@(X*X); warp per row.
// Clamped 8-wide chunks: NO serial tail — out-of-range lanes re-load ed[end-1]
// with val forced to 0, so every edge sees full 8-deep MLP.
__global__ void spmm_kernel(int r) {
    int gw = (blockIdx.x * blockDim.x + threadIdx.x) >> 5;
    int lane = threadIdx.x & 31;
    if (gw >= NN) return;
    const u64* __restrict__ ed = g_edge[r];
    int beg = g_rowptr[r][gw]     + g_blk[r][gw >> 10];
    int end = g_rowptr[r][gw + 1] + g_blk[r][(gw + 1) >> 10];
    u64 a = 0ull, b = 0ull;
    int last = end - 1;
    for (int e = beg; e < end; e += 8) {
        u64 p[8], x[8], vv[8];
        #pragma unroll
        for (int j = 0; j < 8; j++) {
            int idx = e + j;
            p[j] = ed[idx < end ? idx : last];
        }
        #pragma unroll
        for (int j = 0; j < 8; j++)
            x[j] = *(const u64*)&g_X[(size_t)(uint32_t)p[j] * D + 2 * lane];
        #pragma unroll
        for (int j = 0; j < 8; j++) {
            float vf = (e + j < end) ? __uint_as_float((uint32_t)(p[j] >> 32)) : 0.f;
            vv[j] = f2dup(vf);
        }
        #pragma unroll
        for (int j = 0; j < 8; j++) {
            a = ffma2(vv[j], x[j], a);
            b = ffma2(vv[j], fmul2(x[j], x[j]), b);
        }
    }
    u64 xr = *(const u64*)&g_X[(size_t)gw * D + 2 * lane];
    a = fadd2(a, xr);

    float a0, a1, b0, b1;
    funpack2(a, a0, a1);
    funpack2(b, b0, b1);
    uint32_t hi, lo;
    size_t idx = (size_t)gw * 32 + lane;
    split2(a0, a1, hi, lo);
    g_Ah[r][idx] = hi;  g_Al[r][idx] = lo;
    split2(b0, b1, hi, lo);
    g_A2h[r][idx] = hi; g_A2l[r][idx] = lo;
}

// ---------------- HMMA GEMM (pre-converted weights, ~93 KB smem, 2 blocks/SM) ----------------
#define BUF_H  0
#define BUF_L  18432
#define OFF_WLH 36864
#define OFF_WLL 46080
#define OFF_WIH 55296
#define OFF_WIL 64512
#define OFF_WAH 73728
#define OFF_WAL 82944
#define OFF_B12 92160
#define OFF_BA  92416
#define OFF_AV  92672
#define GEMM_SMEM_BYTES 92928

__device__ __forceinline__ void stage_pair(char* smc, const uint32_t* __restrict__ gh,
                                           const uint32_t* __restrict__ gl,
                                           int rowBase, int t) {
    uint32_t* bh = (uint32_t*)(smc + BUF_H);
    uint32_t* bl = (uint32_t*)(smc + BUF_L);
    #pragma unroll
    for (int i = t; i < 4096; i += 256) {
        int row = i >> 5, c = i & 31;
        int grow = rowBase + row;
        uint32_t vh = 0, vl = 0;
        if (grow < NN) {
            vh = gh[(size_t)grow * 32 + c];
            vl = gl[(size_t)grow * 32 + c];
        }
        bh[row * STRDW + c] = vh;
        bl[row * STRDW + c] = vl;
    }
}

__global__ void __launch_bounds__(256) gemm_mma_kernel(
    int l, int r,
    const float* __restrict__ lin_b, const float* __restrict__ inter_b,
    const float* __restrict__ attb0, const float* __restrict__ attb1, const float* __restrict__ attb2,
    const float* __restrict__ av0,   const float* __restrict__ av1,   const float* __restrict__ av2)
{
    extern __shared__ char smc[];
    uint32_t sbase = smem_to_u32(smc);

    const float* attb = ((r == 0) ? attb0 : (r == 1) ? attb1 : attb2) + l * 64;
    const float* avec = ((r == 0) ? av0   : (r == 1) ? av1   : av2)   + l * 64;

    int t = threadIdx.x, wid = t >> 5, lane = t & 31;
    int warpRow = wid * 16;
    int rowBase = blockIdx.x * 128;

    {
        const uint4* __restrict__ wsrc = &g_Wpack[l][0][0];
        uint4* wdst = (uint4*)(smc + OFF_WLH);
        #pragma unroll 4
        for (int i = t; i < 6 * 576; i += 256) {
            int a = i / 576, o = i - a * 576;
            int ga = (a < 4) ? a : (4 + 2 * r + (a - 4));
            wdst[a * 576 + o] = wsrc[ga * 576 + o];
        }
    }
    if (t < 64) {
        ((float*)(smc + OFF_B12))[t] = lin_b[l * 64 + t] + inter_b[l * 64 + t];
        ((float*)(smc + OFF_BA))[t]  = attb[t];
        ((float*)(smc + OFF_AV))[t]  = avec[t];
    }

    stage_pair(smc, g_Ah[r], g_Al[r], rowBase, t);
    __syncthreads();

    float acc[8][4];
    #pragma unroll
    for (int n = 0; n < 8; n++)
        #pragma unroll
        for (int q = 0; q < 4; q++) acc[n][q] = 0.f;

    int lr = lane & 15, kh = lane >> 4;
    int gid = lane >> 2, qk = lane & 3;

    #pragma unroll
    for (int kt = 0; kt < 4; kt++) {
        uint32_t rowoff = (uint32_t)((warpRow + lr) * STRD + kt * 16 + kh * 8) * 2;
        uint32_t aH[4], aL[4];
        ldsm4(aH, sbase + BUF_H + rowoff);
        ldsm4(aL, sbase + BUF_L + rowoff);
        #pragma unroll
        for (int nt = 0; nt < 8; nt++) {
            uint32_t wb = (uint32_t)((nt * 8 + gid) * STRD + kt * 16 + qk * 2) * 2;
            uint32_t bWLh[2], bWLl[2];
            bWLh[0] = lds32(sbase + OFF_WLH + wb); bWLh[1] = lds32(sbase + OFF_WLH + wb + 16);
            bWLl[0] = lds32(sbase + OFF_WLL + wb); bWLl[1] = lds32(sbase + OFF_WLL + wb + 16);
            mma16816(acc[nt], aH, bWLh);
            mma16816(acc[nt], aH, bWLl);
            mma16816(acc[nt], aL, bWLh);
        }
    }
    __syncthreads();

    stage_pair(smc, g_A2h[r], g_A2l[r], rowBase, t);
    __syncthreads();

    #pragma unroll
    for (int kt = 0; kt < 4; kt++) {
        uint32_t rowoff = (uint32_t)((warpRow + lr) * STRD + kt * 16 + kh * 8) * 2;
        uint32_t aH[4], aL[4];
        ldsm4(aH, sbase + BUF_H + rowoff);
        ldsm4(aL, sbase + BUF_L + rowoff);
        #pragma unroll
        for (int nt = 0; nt < 8; nt++) {
            uint32_t wb = (uint32_t)((nt * 8 + gid) * STRD + kt * 16 + qk * 2) * 2;
            uint32_t bWIh[2], bWIl[2];
            bWIh[0] = lds32(sbase + OFF_WIH + wb); bWIh[1] = lds32(sbase + OFF_WIH + wb + 16);
            bWIl[0] = lds32(sbase + OFF_WIL + wb); bWIl[1] = lds32(sbase + OFF_WIL + wb + 16);
            mma16816(acc[nt], aH, bWIh);
            mma16816(acc[nt], aH, bWIl);
            mma16816(acc[nt], aL, bWIh);
        }
    }
    __syncthreads();

    const float* b12 = (const float*)(smc + OFF_B12);
    float* __restrict__ h12out = g_h12[r];
    int row0 = rowBase + warpRow + gid;
    int row1 = row0 + 8;
    #pragma unroll
    for (int nt = 0; nt < 8; nt++) {
        int col = nt * 8 + qk * 2;
        float h00 = acc[nt][0] + b12[col], h01 = acc[nt][1] + b12[col + 1];
        float h10 = acc[nt][2] + b12[col], h11 = acc[nt][3] + b12[col + 1];
        if (row0 < NN) *(float2*)&h12out[(size_t)row0 * 64 + col] = make_float2(h00, h01);
        if (row1 < NN) *(float2*)&h12out[(size_t)row1 * 64 + col] = make_float2(h10, h11);
        uint32_t hi, lo;
        uint32_t so0 = (uint32_t)((warpRow + gid) * STRD + col) * 2;
        uint32_t so1 = (uint32_t)((warpRow + gid + 8) * STRD + col) * 2;
        split2(h00, h01, hi, lo);
        *(uint32_t*)(smc + BUF_H + so0) = hi;
        *(uint32_t*)(smc + BUF_L + so0) = lo;
        split2(h10, h11, hi, lo);
        *(uint32_t*)(smc + BUF_H + so1) = hi;
        *(uint32_t*)(smc + BUF_L + so1) = lo;
    }
    __syncwarp();

    float zac[8][4];
    #pragma unroll
    for (int n = 0; n < 8; n++)
        #pragma unroll
        for (int q = 0; q < 4; q++) zac[n][q] = 0.f;

    #pragma unroll
    for (int kt = 0; kt < 4; kt++) {
        uint32_t rowoff = (uint32_t)((warpRow + lr) * STRD + kt * 16 + kh * 8) * 2;
        uint32_t hH[4], hL[4];
        ldsm4(hH, sbase + BUF_H + rowoff);
        ldsm4(hL, sbase + BUF_L + rowoff);
        #pragma unroll
        for (int nt = 0; nt < 8; nt++) {
            uint32_t wb = (uint32_t)((nt * 8 + gid) * STRD + kt * 16 + qk * 2) * 2;
            uint32_t bWAh[2], bWAl[2];
            bWAh[0] = lds32(sbase + OFF_WAH + wb); bWAh[1] = lds32(sbase + OFF_WAH + wb + 16);
            bWAl[0] = lds32(sbase + OFF_WAL + wb); bWAl[1] = lds32(sbase + OFF_WAL + wb + 16);
            mma16816(zac[nt], hH, bWAh);
            mma16816(zac[nt], hH, bWAl);
            mma16816(zac[nt], hL, bWAh);
        }
    }

    const float* bA = (const float*)(smc + OFF_BA);
    const float* aV = (const float*)(smc + OFF_AV);
    float attLocal = 0.f;
    bool v0 = row0 < NN, v1 = row1 < NN;
    #pragma unroll
    for (int nt = 0; nt < 8; nt++) {
        int col = nt * 8 + qk * 2;
        float avc0 = aV[col], avc1 = aV[col + 1];
        float bc0 = bA[col], bc1 = bA[col + 1];
        if (v0) attLocal += tanhf(zac[nt][0] + bc0) * avc0 + tanhf(zac[nt][1] + bc1) * avc1;
        if (v1) attLocal += tanhf(zac[nt][2] + bc0) * avc0 + tanhf(zac[nt][3] + bc1) * avc1;
    }
    #pragma unroll
    for (int off = 16; off; off >>= 1)
        attLocal += __shfl_down_sync(0xffffffffu, attLocal, off);
    if (lane == 0) atomicAdd(&g_attsum[l][r], attLocal);
}

// ---------------- combine (+ fused beta softmax; l0 derives facc from X_old) -----
__global__ void __launch_bounds__(512) combine_kernel(int l, float* __restrict__ finalOut) {
    __shared__ float betas[3];
    if (threadIdx.x == 0) {
        float m = g_attsum[l][0] / (float)NN;
        float t = g_attsum[l][1] / (float)NN;
        float a = g_attsum[l][2] / (float)NN;
        float mx = fmaxf(m, fmaxf(a, t));
        float e0 = expf(m - mx), e1 = expf(a - mx), e2 = expf(t - mx);
        float s = e0 + e1 + e2;
        betas[0] = e0 / s;
        betas[1] = e2 / s;
        betas[2] = e1 / s;
    }
    __syncthreads();
    float b0 = betas[0], b1 = betas[1], b2 = betas[2];
    for (int i = blockIdx.x * blockDim.x + threadIdx.x; i < NN * D / 4;
         i += gridDim.x * blockDim.x) {
        float4 h0 = ((const float4*)g_h12[0])[i];
        float4 h1 = ((const float4*)g_h12[1])[i];
        float4 h2 = ((const float4*)g_h12[2])[i];
        float4 v;
        v.x = b0 * h0.x + b1 * h1.x + b2 * h2.x;
        v.y = b0 * h0.y + b1 * h1.y + b2 * h2.y;
        v.z = b0 * h0.z + b1 * h1.z + b2 * h2.z;
        v.w = b0 * h0.w + b1 * h1.w + b2 * h2.w;
        if (l == 0) {
            float4 x = ((const float4*)g_X)[i];
            float4 f;
            f.x = x.x + v.x; f.y = x.y + v.y; f.z = x.z + v.z; f.w = x.w + v.w;
            ((float4*)g_facc)[i] = f;
            ((float4*)g_X)[i] = v;
        } else {
            float4 f = ((const float4*)g_facc)[i];
            const float k = 1.0f / 3.0f;
            v.x = (f.x + v.x) * k;
            v.y = (f.y + v.y) * k;
            v.z = (f.z + v.z) * k;
            v.w = (f.w + v.w) * k;
            ((float4*)finalOut)[i] = v;
        }
    }
}

__global__ void mlp_kernel(const int* __restrict__ userIdx, const int* __restrict__ itemIdx,
                           const float* __restrict__ W1, const float* __restrict__ b1,
                           const float* __restrict__ W2, const float* __restrict__ b2,
                           const float* __restrict__ W3, const float* __restrict__ b3,
                           const float* __restrict__ finalE,
                           float* __restrict__ pred, float* __restrict__ outU, float* __restrict__ outI)
{
    __shared__ float h[128];
    __shared__ float h1s[64];
    __shared__ float h2s[32];
    int bI = blockIdx.x;
    int t = threadIdx.x;
    int u = userIdx[bI];
    int v = itemIdx[bI] + N_USER;
    float fu = finalE[u * D + t];
    float fi = finalE[v * D + t];
    h[t] = fu; h[64 + t] = fi;
    outU[bI * D + t] = fu;
    outI[bI * D + t] = fi;
    __syncthreads();

    float acc = b1[t];
    #pragma unroll 16
    for (int k = 0; k < 128; k++) acc += h[k] * W1[k * 64 + t];
    h1s[t] = fmaxf(acc, 0.f);
    __syncthreads();

    if (t < 32) {
        float a2 = b2[t];
        #pragma unroll 16
        for (int k = 0; k < 64; k++) a2 += h1s[k] * W2[k * 32 + t];
        h2s[t] = a2;
    }
    __syncthreads();
    if (t < 32) {
        float p = h2s[t] * W3[t];
        #pragma unroll
        for (int off = 16; off; off >>= 1) p += __shfl_down_sync(0xffffffffu, p, off);
        if (t == 0) pred[bI] = p + b3[0];
    }
}

// ---------------- launch ----------------
extern "C" void kernel_launch(void* const* d_in, const int* in_sizes, int n_in,
                              void* d_out, int out_size)
{
    const int*   userIdx = (const int*)d_in[0];
    const int*   itemIdx = (const int*)d_in[1];
    const float* uEmbd   = (const float*)d_in[2];
    const float* iEmbd   = (const float*)d_in[3];

    const int*   rowP[3] = { (const int*)d_in[4],  (const int*)d_in[7],  (const int*)d_in[10] };
    const int*   colP[3] = { (const int*)d_in[5],  (const int*)d_in[8],  (const int*)d_in[11] };
    const float* valP[3] = { (const float*)d_in[6], (const float*)d_in[9], (const float*)d_in[12] };

    const float *lin_W, *lin_b, *inter_W, *inter_b;
    const float *attM_W, *attM_b, *attA_W, *attA_b, *attT_W, *attT_b;
    if (in_sizes[14] == 2 * D * D) {
        lin_W   = (const float*)d_in[13];
        inter_W = (const float*)d_in[14];
        attM_W  = (const float*)d_in[15];
        attA_W  = (const float*)d_in[16];
        attT_W  = (const float*)d_in[17];
        lin_b   = (const float*)d_in[18];
        inter_b = (const float*)d_in[19];
        attM_b  = (const float*)d_in[20];
        attA_b  = (const float*)d_in[21];
        attT_b  = (const float*)d_in[22];
    } else {
        lin_W   = (const float*)d_in[13];
        lin_b   = (const float*)d_in[14];
        inter_W = (const float*)d_in[15];
        inter_b = (const float*)d_in[16];
        attM_W  = (const float*)d_in[17];
        attM_b  = (const float*)d_in[18];
        attA_W  = (const float*)d_in[19];
        attA_b  = (const float*)d_in[20];
        attT_W  = (const float*)d_in[21];
        attT_b  = (const float*)d_in[22];
    }
    const float* a_main  = (const float*)d_in[23];
    const float* a_add   = (const float*)d_in[24];
    const float* a_trust = (const float*)d_in[25];
    const float* W1 = (const float*)d_in[26];
    const float* b1 = (const float*)d_in[27];
    const float* W2 = (const float*)d_in[28];
    const float* b2 = (const float*)d_in[29];
    const float* W3 = (const float*)d_in[30];
    const float* b3 = (const float*)d_in[31];

    float* out      = (float*)d_out;
    float* predOut  = out;
    float* userOut  = out + BB;
    float* itemOut  = out + BB + BB * D;
    float* finalOut = out + BB + 2 * BB * D;

    const int TPB = 256;
    const int SETUP_BLOCKS = (NN * D / 4 + TPB - 1) / TPB;
    const int E8_BLOCKS = (NNZ / 8 + TPB - 1) / TPB;
    const int E4_BLOCKS = (NNZ / 4 + TPB - 1) / TPB;
    const int SPMM_BLOCKS = (NN * 32 + TPB - 1) / TPB;
    const int GEMM_BLOCKS = (NN + 127) / 128;
    const int COMB_BLOCKS = 592;

    static cudaStream_t st[3];
    static cudaEvent_t evStart, evReady, evL[NLAYERS][3], evC;
    static bool inited = false;
    if (!inited) {
        for (int r = 0; r < 3; r++) cudaStreamCreateWithFlags(&st[r], cudaStreamNonBlocking);
        cudaEventCreateWithFlags(&evStart, cudaEventDisableTiming);
        cudaEventCreateWithFlags(&evReady, cudaEventDisableTiming);
        cudaEventCreateWithFlags(&evC, cudaEventDisableTiming);
        for (int l = 0; l < NLAYERS; l++)
            for (int r = 0; r < 3; r++)
                cudaEventCreateWithFlags(&evL[l][r], cudaEventDisableTiming);
        cudaFuncSetAttribute(gemm_mma_kernel, cudaFuncAttributeMaxDynamicSharedMemorySize,
                             GEMM_SMEM_BYTES);
        inited = true;
    }

    cudaEventRecord(evStart, 0);
    for (int r = 0; r < 3; r++) {
        cudaStreamWaitEvent(st[r], evStart, 0);
        hist_kernel<<<E4_BLOCKS, TPB, 0, st[r]>>>(rowP[r], r);
        scan_local_kernel<<<NB, 1024, 0, st[r]>>>(r);
        scan_blk_kernel<<<1, 128, 0, st[r]>>>(r);
        scatter_kernel<<<E8_BLOCKS, TPB, 0, st[r]>>>(rowP[r], colP[r], valP[r], r);
    }

    setup_kernel<<<SETUP_BLOCKS, TPB>>>(uEmbd, iEmbd);
    wconv_kernel<<<dim3(NLAYERS, 5), 256>>>(lin_W, inter_W, attM_W, attT_W, attA_W);
    cudaEventRecord(evReady, 0);

    for (int r = 0; r < 3; r++) {
        cudaStreamWaitEvent(st[r], evReady, 0);
        spmm_kernel<<<SPMM_BLOCKS, TPB, 0, st[r]>>>(r);
        gemm_mma_kernel<<<GEMM_BLOCKS, 256, GEMM_SMEM_BYTES, st[r]>>>(
            0, r, lin_b, inter_b, attM_b, attT_b, attA_b, a_main, a_trust, a_add);
        cudaEventRecord(evL[0][r], st[r]);
    }
    for (int r = 0; r < 3; r++) cudaStreamWaitEvent(0, evL[0][r], 0);
    combine_kernel<<<COMB_BLOCKS, 512>>>(0, finalOut);
    cudaEventRecord(evC, 0);

    for (int r = 0; r < 3; r++) {
        cudaStreamWaitEvent(st[r], evC, 0);
        spmm_kernel<<<SPMM_BLOCKS, TPB, 0, st[r]>>>(r);
        gemm_mma_kernel<<<GEMM_BLOCKS, 256, GEMM_SMEM_BYTES, st[r]>>>(
            1, r, lin_b, inter_b, attM_b, attT_b, attA_b, a_main, a_trust, a_add);
        cudaEventRecord(evL[1][r], st[r]);
    }
    for (int r = 0; r < 3; r++) cudaStreamWaitEvent(0, evL[1][r], 0);
    combine_kernel<<<COMB_BLOCKS, 512>>>(1, finalOut);

    mlp_kernel<<<BB, 64>>>(userIdx, itemIdx, W1, b1, W2, b2, W3, b3,
                           finalOut, predOut, userOut, itemOut);
}

// round 14
// speedup vs baseline: 1.0896x; 1.0896x over previous
#include <cuda_runtime.h>
#include <cuda_bf16.h>
#include <math.h>
#include <stdint.h>

#define N_USER 60000
#define N_ITEM 40000
#define NN     100000
#define D      64
#define NNZ    1600000
#define BB     16384
#define NLAYERS 2
#define NB     98          // ceil(NN/1024)

typedef unsigned long long u64;

// ---------------- packed f32x2 helpers ----------------
__device__ __forceinline__ u64 f2dup(float v) {
    u64 r; asm("mov.b64 %0,{%1,%1};" : "=l"(r) : "f"(v)); return r;
}
__device__ __forceinline__ u64 ffma2(u64 a, u64 b, u64 c) {
    u64 d; asm("fma.rn.f32x2 %0,%1,%2,%3;" : "=l"(d) : "l"(a), "l"(b), "l"(c)); return d;
}
__device__ __forceinline__ u64 fmul2(u64 a, u64 b) {
    u64 d; asm("mul.rn.f32x2 %0,%1,%2;" : "=l"(d) : "l"(a), "l"(b)); return d;
}
__device__ __forceinline__ u64 fadd2(u64 a, u64 b) {
    u64 d; asm("add.rn.f32x2 %0,%1,%2;" : "=l"(d) : "l"(a), "l"(b)); return d;
}
__device__ __forceinline__ void funpack2(u64 v, float& lo, float& hi) {
    asm("mov.b64 {%0,%1},%2;" : "=f"(lo), "=f"(hi) : "l"(v));
}

// ---------------- mma.sync helpers ----------------
__device__ __forceinline__ uint32_t smem_to_u32(const void* p) {
    uint32_t a;
    asm("{ .reg .u64 t; cvta.to.shared.u64 t, %1; cvt.u32.u64 %0, t; }" : "=r"(a) : "l"(p));
    return a;
}
__device__ __forceinline__ void ldsm4(uint32_t* r, uint32_t addr) {
    asm volatile("ldmatrix.sync.aligned.m8n8.x4.shared.b16 {%0,%1,%2,%3}, [%4];"
        : "=r"(r[0]), "=r"(r[1]), "=r"(r[2]), "=r"(r[3]) : "r"(addr));
}
__device__ __forceinline__ uint32_t lds32(uint32_t addr) {
    uint32_t v; asm volatile("ld.shared.b32 %0, [%1];" : "=r"(v) : "r"(addr)); return v;
}
__device__ __forceinline__ void mma16816(float* d, const uint32_t* a, const uint32_t* b) {
    asm volatile(
        "mma.sync.aligned.m16n8k16.row.col.f32.bf16.bf16.f32 "
        "{%0,%1,%2,%3}, {%4,%5,%6,%7}, {%8,%9}, {%0,%1,%2,%3};"
        : "+f"(d[0]), "+f"(d[1]), "+f"(d[2]), "+f"(d[3])
        : "r"(a[0]), "r"(a[1]), "r"(a[2]), "r"(a[3]), "r"(b[0]), "r"(b[1]));
}

__device__ __forceinline__ void split2(float a, float b, uint32_t& hi, uint32_t& lo) {
    __nv_bfloat16 ah = __float2bfloat16(a);
    __nv_bfloat16 bh = __float2bfloat16(b);
    __nv_bfloat16 al = __float2bfloat16(a - __bfloat162float(ah));
    __nv_bfloat16 bl = __float2bfloat16(b - __bfloat162float(bh));
    hi = (uint32_t)__bfloat16_as_ushort(ah) | ((uint32_t)__bfloat16_as_ushort(bh) << 16);
    lo = (uint32_t)__bfloat16_as_ushort(al) | ((uint32_t)__bfloat16_as_ushort(bl) << 16);
}

#define STRD 72
#define STRDW 36

// ---------------- scratch ----------------
__device__ float g_X[NN * D];
__device__ float g_facc[NN * D];
__device__ float g_h12[3][NN * D];
__device__ u64   g_A[3][NN * 32];       // packed: lo32 = (S+X) hi-split, hi32 = lo-split
__device__ u64   g_A2[3][NN * 32];      // packed: lo32 = S2 hi-split,   hi32 = lo-split
__device__ int   g_rowptr[3][NN + 1];   // block-LOCAL exclusive scans (+blk at use)
__device__ u64   g_edge[3][NNZ];
__device__ int   g_count3[3][NN];       // zero-init; scan_local re-zeroes after read
__device__ int   g_cursor3[3][NN];      // block-local cursors
__device__ int   g_blk[3][128];         // per-block exclusive offsets
__device__ float g_attsum[NLAYERS][3];
__device__ uint4 g_Wpack[NLAYERS][10][576];

// ---------------- setup: zero attsums, init X ----------------
__global__ void setup_kernel(const float* __restrict__ uE, const float* __restrict__ iE) {
    int i = blockIdx.x * blockDim.x + threadIdx.x;
    if (i < NLAYERS * 3) ((float*)g_attsum)[i] = 0.f;
    if (i < NN * D / 4) {
        int j = i * 4;
        float4 v = (j < N_USER * D) ? ((const float4*)uE)[i]
                                    : ((const float4*)iE)[i - N_USER * D / 4];
        ((float4*)g_X)[i] = v;
    }
}

// ---------------- weight pre-conversion (once per launch) ----------------
__global__ void wconv_kernel(const float* __restrict__ linW, const float* __restrict__ intW,
                             const float* __restrict__ aW0, const float* __restrict__ aW1,
                             const float* __restrict__ aW2) {
    int l = blockIdx.x, m = blockIdx.y;
    const float* src = (m == 0) ? linW : (m == 1) ? intW
                      : (m == 2) ? aW0 : (m == 3) ? aW1 : aW2;
    src += l * 4096;
    unsigned short* dh = (unsigned short*)&g_Wpack[l][m * 2][0];
    unsigned short* dl = (unsigned short*)&g_Wpack[l][m * 2 + 1][0];
    for (int i = threadIdx.x; i < 4096; i += 256) {
        int k = i >> 6, n = i & 63;
        float w = src[i];
        __nv_bfloat16 h = __float2bfloat16(w);
        dh[n * STRD + k] = __bfloat16_as_ushort(h);
        dl[n * STRD + k] = __bfloat16_as_ushort(__float2bfloat16(w - __bfloat162float(h)));
    }
}

// ---------------- CSR build (per-relation) ----------------
__global__ void hist_kernel(const int* __restrict__ row, int r) {
    int e4 = blockIdx.x * blockDim.x + threadIdx.x;
    if (e4 < NNZ / 4) {
        int4 rr = ((const int4*)row)[e4];
        atomicAdd(&g_count3[r][rr.x], 1);
        atomicAdd(&g_count3[r][rr.y], 1);
        atomicAdd(&g_count3[r][rr.z], 1);
        atomicAdd(&g_count3[r][rr.w], 1);
    }
}

__global__ void scan_local_kernel(int r) {
    __shared__ int s[1024];
    int i = blockIdx.x * 1024 + threadIdx.x;
    int c = 0;
    if (i < NN) {
        c = g_count3[r][i];
        g_count3[r][i] = 0;            // reset for next graph replay
    }
    s[threadIdx.x] = c;
    __syncthreads();
    for (int off = 1; off < 1024; off <<= 1) {
        int t = (threadIdx.x >= off) ? s[threadIdx.x - off] : 0;
        __syncthreads();
        s[threadIdx.x] += t;
        __syncthreads();
    }
    if (i < NN) {
        int excl = s[threadIdx.x] - c;
        g_rowptr[r][i]  = excl;
        g_cursor3[r][i] = excl;
    }
    if (threadIdx.x == 1023) g_blk[r][blockIdx.x] = s[1023];
}

__global__ void scan_blk_kernel(int r) {
    __shared__ int s[128];
    int tid = threadIdx.x;
    int v = (tid < NB) ? g_blk[r][tid] : 0;
    s[tid] = v;
    __syncthreads();
    for (int off = 1; off < 128; off <<= 1) {
        int t = (tid >= off) ? s[tid - off] : 0;
        __syncthreads();
        s[tid] += t;
        __syncthreads();
    }
    if (tid < NB) g_blk[r][tid] = s[tid] - v;
    if (tid == NB - 1) g_rowptr[r][NN] = v;
}

__global__ void scatter_kernel(const int* __restrict__ row, const int* __restrict__ col,
                               const float* __restrict__ val, int r) {
    int e4 = blockIdx.x * blockDim.x + threadIdx.x;
    if (e4 < NNZ / 4) {
        int4   rr = ((const int4*)row)[e4];
        int4   cc = ((const int4*)col)[e4];
        float4 vv = ((const float4*)val)[e4];
        u64* __restrict__ ed = g_edge[r];
        const int* __restrict__ blk = g_blk[r];
        int p;
        p = atomicAdd(&g_cursor3[r][rr.x], 1) + blk[rr.x >> 10];
        ed[p] = ((u64)(uint32_t)__float_as_int(vv.x) << 32) | (uint32_t)cc.x;
        p = atomicAdd(&g_cursor3[r][rr.y], 1) + blk[rr.y >> 10];
        ed[p] = ((u64)(uint32_t)__float_as_int(vv.y) << 32) | (uint32_t)cc.y;
        p = atomicAdd(&g_cursor3[r][rr.z], 1) + blk[rr.z >> 10];
        ed[p] = ((u64)(uint32_t)__float_as_int(vv.z) << 32) | (uint32_t)cc.z;
        p = atomicAdd(&g_cursor3[r][rr.w], 1) + blk[rr.w >> 10];
        ed[p] = ((u64)(uint32_t)__float_as_int(vv.w) << 32) | (uint32_t)cc.w;
    }
}

// fused SpMM: A = L@X + X, A2 = L@(X*X); warp per row; 8-deep gather pipeline
__global__ void spmm_kernel(int r) {
    int gw = (blockIdx.x * blockDim.x + threadIdx.x) >> 5;
    int lane = threadIdx.x & 31;
    if (gw >= NN) return;
    const u64* __restrict__ ed = g_edge[r];
    int beg = g_rowptr[r][gw]     + g_blk[r][gw >> 10];
    int end = g_rowptr[r][gw + 1] + g_blk[r][(gw + 1) >> 10];
    u64 a = 0ull, b = 0ull;
    int e = beg;
    for (; e + 8 <= end; e += 8) {
        u64 p0 = ed[e],     p1 = ed[e + 1], p2 = ed[e + 2], p3 = ed[e + 3];
        u64 p4 = ed[e + 4], p5 = ed[e + 5], p6 = ed[e + 6], p7 = ed[e + 7];
        u64 x0 = *(const u64*)&g_X[(size_t)(uint32_t)p0 * D + 2 * lane];
        u64 x1 = *(const u64*)&g_X[(size_t)(uint32_t)p1 * D + 2 * lane];
        u64 x2 = *(const u64*)&g_X[(size_t)(uint32_t)p2 * D + 2 * lane];
        u64 x3 = *(const u64*)&g_X[(size_t)(uint32_t)p3 * D + 2 * lane];
        u64 x4 = *(const u64*)&g_X[(size_t)(uint32_t)p4 * D + 2 * lane];
        u64 x5 = *(const u64*)&g_X[(size_t)(uint32_t)p5 * D + 2 * lane];
        u64 x6 = *(const u64*)&g_X[(size_t)(uint32_t)p6 * D + 2 * lane];
        u64 x7 = *(const u64*)&g_X[(size_t)(uint32_t)p7 * D + 2 * lane];
        u64 v0 = f2dup(__uint_as_float((uint32_t)(p0 >> 32)));
        u64 v1 = f2dup(__uint_as_float((uint32_t)(p1 >> 32)));
        u64 v2 = f2dup(__uint_as_float((uint32_t)(p2 >> 32)));
        u64 v3 = f2dup(__uint_as_float((uint32_t)(p3 >> 32)));
        u64 v4 = f2dup(__uint_as_float((uint32_t)(p4 >> 32)));
        u64 v5 = f2dup(__uint_as_float((uint32_t)(p5 >> 32)));
        u64 v6 = f2dup(__uint_as_float((uint32_t)(p6 >> 32)));
        u64 v7 = f2dup(__uint_as_float((uint32_t)(p7 >> 32)));
        a = ffma2(v0, x0, a); b = ffma2(v0, fmul2(x0, x0), b);
        a = ffma2(v1, x1, a); b = ffma2(v1, fmul2(x1, x1), b);
        a = ffma2(v2, x2, a); b = ffma2(v2, fmul2(x2, x2), b);
        a = ffma2(v3, x3, a); b = ffma2(v3, fmul2(x3, x3), b);
        a = ffma2(v4, x4, a); b = ffma2(v4, fmul2(x4, x4), b);
        a = ffma2(v5, x5, a); b = ffma2(v5, fmul2(x5, x5), b);
        a = ffma2(v6, x6, a); b = ffma2(v6, fmul2(x6, x6), b);
        a = ffma2(v7, x7, a); b = ffma2(v7, fmul2(x7, x7), b);
    }
    for (; e < end; e++) {
        u64 p0 = ed[e];
        u64 x0 = *(const u64*)&g_X[(size_t)(uint32_t)p0 * D + 2 * lane];
        u64 v0 = f2dup(__uint_as_float((uint32_t)(p0 >> 32)));
        a = ffma2(v0, x0, a); b = ffma2(v0, fmul2(x0, x0), b);
    }
    u64 xr = *(const u64*)&g_X[(size_t)gw * D + 2 * lane];
    a = fadd2(a, xr);

    float a0, a1, b0, b1;
    funpack2(a, a0, a1);
    funpack2(b, b0, b1);
    uint32_t hi, lo;
    size_t idx = (size_t)gw * 32 + lane;
    split2(a0, a1, hi, lo);
    g_A[r][idx]  = ((u64)lo << 32) | hi;
    split2(b0, b1, hi, lo);
    g_A2[r][idx] = ((u64)lo << 32) | hi;
}

// ---------------- HMMA GEMM (pre-converted weights, ~93 KB smem, 2 blocks/SM) ----------------
#define BUF_H  0
#define BUF_L  18432
#define OFF_WLH 36864
#define OFF_WLL 46080
#define OFF_WIH 55296
#define OFF_WIL 64512
#define OFF_WAH 73728
#define OFF_WAL 82944
#define OFF_B12 92160
#define OFF_BA  92416
#define OFF_AV  92672
#define GEMM_SMEM_BYTES 92928

__device__ __forceinline__ void stage_pair(char* smc, const u64* __restrict__ gp,
                                           int rowBase, int t) {
    uint32_t* bh = (uint32_t*)(smc + BUF_H);
    uint32_t* bl = (uint32_t*)(smc + BUF_L);
    #pragma unroll
    for (int i = t; i < 4096; i += 256) {
        int row = i >> 5, c = i & 31;
        int grow = rowBase + row;
        u64 v = 0ull;
        if (grow < NN) v = gp[(size_t)grow * 32 + c];
        bh[row * STRDW + c] = (uint32_t)v;
        bl[row * STRDW + c] = (uint32_t)(v >> 32);
    }
}

__global__ void __launch_bounds__(256) gemm_mma_kernel(
    int l, int r,
    const float* __restrict__ lin_b, const float* __restrict__ inter_b,
    const float* __restrict__ attb0, const float* __restrict__ attb1, const float* __restrict__ attb2,
    const float* __restrict__ av0,   const float* __restrict__ av1,   const float* __restrict__ av2)
{
    extern __shared__ char smc[];
    uint32_t sbase = smem_to_u32(smc);

    const float* attb = ((r == 0) ? attb0 : (r == 1) ? attb1 : attb2) + l * 64;
    const float* avec = ((r == 0) ? av0   : (r == 1) ? av1   : av2)   + l * 64;

    int t = threadIdx.x, wid = t >> 5, lane = t & 31;
    int warpRow = wid * 16;
    int rowBase = blockIdx.x * 128;

    {
        const uint4* __restrict__ wsrc = &g_Wpack[l][0][0];
        uint4* wdst = (uint4*)(smc + OFF_WLH);
        #pragma unroll 4
        for (int i = t; i < 6 * 576; i += 256) {
            int a = i / 576, o = i - a * 576;
            int ga = (a < 4) ? a : (4 + 2 * r + (a - 4));
            wdst[a * 576 + o] = wsrc[ga * 576 + o];
        }
    }
    if (t < 64) {
        ((float*)(smc + OFF_B12))[t] = lin_b[l * 64 + t] + inter_b[l * 64 + t];
        ((float*)(smc + OFF_BA))[t]  = attb[t];
        ((float*)(smc + OFF_AV))[t]  = avec[t];
    }

    stage_pair(smc, g_A[r], rowBase, t);
    __syncthreads();

    float acc[8][4];
    #pragma unroll
    for (int n = 0; n < 8; n++)
        #pragma unroll
        for (int q = 0; q < 4; q++) acc[n][q] = 0.f;

    int lr = lane & 15, kh = lane >> 4;
    int gid = lane >> 2, qk = lane & 3;

    #pragma unroll
    for (int kt = 0; kt < 4; kt++) {
        uint32_t rowoff = (uint32_t)((warpRow + lr) * STRD + kt * 16 + kh * 8) * 2;
        uint32_t aH[4], aL[4];
        ldsm4(aH, sbase + BUF_H + rowoff);
        ldsm4(aL, sbase + BUF_L + rowoff);
        #pragma unroll
        for (int nt = 0; nt < 8; nt++) {
            uint32_t wb = (uint32_t)((nt * 8 + gid) * STRD + kt * 16 + qk * 2) * 2;
            uint32_t bWLh[2], bWLl[2];
            bWLh[0] = lds32(sbase + OFF_WLH + wb); bWLh[1] = lds32(sbase + OFF_WLH + wb + 16);
            bWLl[0] = lds32(sbase + OFF_WLL + wb); bWLl[1] = lds32(sbase + OFF_WLL + wb + 16);
            mma16816(acc[nt], aH, bWLh);
            mma16816(acc[nt], aH, bWLl);
            mma16816(acc[nt], aL, bWLh);
        }
    }
    __syncthreads();

    stage_pair(smc, g_A2[r], rowBase, t);
    __syncthreads();

    #pragma unroll
    for (int kt = 0; kt < 4; kt++) {
        uint32_t rowoff = (uint32_t)((warpRow + lr) * STRD + kt * 16 + kh * 8) * 2;
        uint32_t aH[4], aL[4];
        ldsm4(aH, sbase + BUF_H + rowoff);
        ldsm4(aL, sbase + BUF_L + rowoff);
        #pragma unroll
        for (int nt = 0; nt < 8; nt++) {
            uint32_t wb = (uint32_t)((nt * 8 + gid) * STRD + kt * 16 + qk * 2) * 2;
            uint32_t bWIh[2], bWIl[2];
            bWIh[0] = lds32(sbase + OFF_WIH + wb); bWIh[1] = lds32(sbase + OFF_WIH + wb + 16);
            bWIl[0] = lds32(sbase + OFF_WIL + wb); bWIl[1] = lds32(sbase + OFF_WIL + wb + 16);
            mma16816(acc[nt], aH, bWIh);
            mma16816(acc[nt], aH, bWIl);
            mma16816(acc[nt], aL, bWIh);
        }
    }
    __syncthreads();

    const float* b12 = (const float*)(smc + OFF_B12);
    float* __restrict__ h12out = g_h12[r];
    int row0 = rowBase + warpRow + gid;
    int row1 = row0 + 8;
    #pragma unroll
    for (int nt = 0; nt < 8; nt++) {
        int col = nt * 8 + qk * 2;
        float h00 = acc[nt][0] + b12[col], h01 = acc[nt][1] + b12[col + 1];
        float h10 = acc[nt][2] + b12[col], h11 = acc[nt][3] + b12[col + 1];
        if (row0 < NN) *(float2*)&h12out[(size_t)row0 * 64 + col] = make_float2(h00, h01);
        if (row1 < NN) *(float2*)&h12out[(size_t)row1 * 64 + col] = make_float2(h10, h11);
        uint32_t hi, lo;
        uint32_t so0 = (uint32_t)((warpRow + gid) * STRD + col) * 2;
        uint32_t so1 = (uint32_t)((warpRow + gid + 8) * STRD + col) * 2;
        split2(h00, h01, hi, lo);
        *(uint32_t*)(smc + BUF_H + so0) = hi;
        *(uint32_t*)(smc + BUF_L + so0) = lo;
        split2(h10, h11, hi, lo);
        *(uint32_t*)(smc + BUF_H + so1) = hi;
        *(uint32_t*)(smc + BUF_L + so1) = lo;
    }
    __syncwarp();

    float zac[8][4];
    #pragma unroll
    for (int n = 0; n < 8; n++)
        #pragma unroll
        for (int q = 0; q < 4; q++) zac[n][q] = 0.f;

    #pragma unroll
    for (int kt = 0; kt < 4; kt++) {
        uint32_t rowoff = (uint32_t)((warpRow + lr) * STRD + kt * 16 + kh * 8) * 2;
        uint32_t hH[4], hL[4];
        ldsm4(hH, sbase + BUF_H + rowoff);
        ldsm4(hL, sbase + BUF_L + rowoff);
        #pragma unroll
        for (int nt = 0; nt < 8; nt++) {
            uint32_t wb = (uint32_t)((nt * 8 + gid) * STRD + kt * 16 + qk * 2) * 2;
            uint32_t bWAh[2], bWAl[2];
            bWAh[0] = lds32(sbase + OFF_WAH + wb); bWAh[1] = lds32(sbase + OFF_WAH + wb + 16);
            bWAl[0] = lds32(sbase + OFF_WAL + wb); bWAl[1] = lds32(sbase + OFF_WAL + wb + 16);
            mma16816(zac[nt], hH, bWAh);
            mma16816(zac[nt], hH, bWAl);
            mma16816(zac[nt], hL, bWAh);
        }
    }

    const float* bA = (const float*)(smc + OFF_BA);
    const float* aV = (const float*)(smc + OFF_AV);
    float attLocal = 0.f;
    bool v0 = row0 < NN, v1 = row1 < NN;
    #pragma unroll
    for (int nt = 0; nt < 8; nt++) {
        int col = nt * 8 + qk * 2;
        float avc0 = aV[col], avc1 = aV[col + 1];
        float bc0 = bA[col], bc1 = bA[col + 1];
        if (v0) attLocal += tanhf(zac[nt][0] + bc0) * avc0 + tanhf(zac[nt][1] + bc1) * avc1;
        if (v1) attLocal += tanhf(zac[nt][2] + bc0) * avc0 + tanhf(zac[nt][3] + bc1) * avc1;
    }
    #pragma unroll
    for (int off = 16; off; off >>= 1)
        attLocal += __shfl_down_sync(0xffffffffu, attLocal, off);
    if (lane == 0) atomicAdd(&g_attsum[l][r], attLocal);
}

// ---------------- combine (+ fused beta softmax; l0 derives facc from X_old) -----
__global__ void __launch_bounds__(512) combine_kernel(int l, float* __restrict__ finalOut) {
    __shared__ float betas[3];
    if (threadIdx.x == 0) {
        float m = g_attsum[l][0] / (float)NN;
        float t = g_attsum[l][1] / (float)NN;
        float a = g_attsum[l][2] / (float)NN;
        float mx = fmaxf(m, fmaxf(a, t));
        float e0 = expf(m - mx), e1 = expf(a - mx), e2 = expf(t - mx);
        float s = e0 + e1 + e2;
        betas[0] = e0 / s;
        betas[1] = e2 / s;
        betas[2] = e1 / s;
    }
    __syncthreads();
    float b0 = betas[0], b1 = betas[1], b2 = betas[2];
    for (int i = blockIdx.x * blockDim.x + threadIdx.x; i < NN * D / 4;
         i += gridDim.x * blockDim.x) {
        float4 h0 = ((const float4*)g_h12[0])[i];
        float4 h1 = ((const float4*)g_h12[1])[i];
        float4 h2 = ((const float4*)g_h12[2])[i];
        float4 v;
        v.x = b0 * h0.x + b1 * h1.x + b2 * h2.x;
        v.y = b0 * h0.y + b1 * h1.y + b2 * h2.y;
        v.z = b0 * h0.z + b1 * h1.z + b2 * h2.z;
        v.w = b0 * h0.w + b1 * h1.w + b2 * h2.w;
        if (l == 0) {
            float4 x = ((const float4*)g_X)[i];
            float4 f;
            f.x = x.x + v.x; f.y = x.y + v.y; f.z = x.z + v.z; f.w = x.w + v.w;
            ((float4*)g_facc)[i] = f;
            ((float4*)g_X)[i] = v;
        } else {
            float4 f = ((const float4*)g_facc)[i];
            const float k = 1.0f / 3.0f;
            v.x = (f.x + v.x) * k;
            v.y = (f.y + v.y) * k;
            v.z = (f.z + v.z) * k;
            v.w = (f.w + v.w) * k;
            ((float4*)finalOut)[i] = v;
        }
    }
}

// 4 pairs per 256-thread block
__global__ void __launch_bounds__(256) mlp_kernel(
    const int* __restrict__ userIdx, const int* __restrict__ itemIdx,
    const float* __restrict__ W1, const float* __restrict__ b1,
    const float* __restrict__ W2, const float* __restrict__ b2,
    const float* __restrict__ W3, const float* __restrict__ b3,
    const float* __restrict__ finalE,
    float* __restrict__ pred, float* __restrict__ outU, float* __restrict__ outI)
{
    __shared__ float h[4][128];
    __shared__ float h1s[4][64];
    __shared__ float h2s[4][32];
    int g = threadIdx.x >> 6;
    int t = threadIdx.x & 63;
    int bI = blockIdx.x * 4 + g;
    int u = userIdx[bI];
    int v = itemIdx[bI] + N_USER;
    float fu = finalE[(size_t)u * D + t];
    float fi = finalE[(size_t)v * D + t];
    h[g][t] = fu; h[g][64 + t] = fi;
    outU[(size_t)bI * D + t] = fu;
    outI[(size_t)bI * D + t] = fi;
    __syncthreads();

    float acc = b1[t];
    #pragma unroll 16
    for (int k = 0; k < 128; k++) acc += h[g][k] * W1[k * 64 + t];
    h1s[g][t] = fmaxf(acc, 0.f);
    __syncthreads();

    if (t < 32) {
        float a2 = b2[t];
        #pragma unroll 16
        for (int k = 0; k < 64; k++) a2 += h1s[g][k] * W2[k * 32 + t];
        h2s[g][t] = a2;
    }
    __syncthreads();
    if (t < 32) {
        float p = h2s[g][t] * W3[t];
        #pragma unroll
        for (int off = 16; off; off >>= 1) p += __shfl_down_sync(0xffffffffu, p, off);
        if (t == 0) pred[bI] = p + b3[0];
    }
}

// ---------------- launch ----------------
extern "C" void kernel_launch(void* const* d_in, const int* in_sizes, int n_in,
                              void* d_out, int out_size)
{
    const int*   userIdx = (const int*)d_in[0];
    const int*   itemIdx = (const int*)d_in[1];
    const float* uEmbd   = (const float*)d_in[2];
    const float* iEmbd   = (const float*)d_in[3];

    const int*   rowP[3] = { (const int*)d_in[4],  (const int*)d_in[7],  (const int*)d_in[10] };
    const int*   colP[3] = { (const int*)d_in[5],  (const int*)d_in[8],  (const int*)d_in[11] };
    const float* valP[3] = { (const float*)d_in[6], (const float*)d_in[9], (const float*)d_in[12] };

    const float *lin_W, *lin_b, *inter_W, *inter_b;
    const float *attM_W, *attM_b, *attA_W, *attA_b, *attT_W, *attT_b;
    if (in_sizes[14] == 2 * D * D) {
        lin_W   = (const float*)d_in[13];
        inter_W = (const float*)d_in[14];
        attM_W  = (const float*)d_in[15];
        attA_W  = (const float*)d_in[16];
        attT_W  = (const float*)d_in[17];
        lin_b   = (const float*)d_in[18];
        inter_b = (const float*)d_in[19];
        attM_b  = (const float*)d_in[20];
        attA_b  = (const float*)d_in[21];
        attT_b  = (const float*)d_in[22];
    } else {
        lin_W   = (const float*)d_in[13];
        lin_b   = (const float*)d_in[14];
        inter_W = (const float*)d_in[15];
        inter_b = (const float*)d_in[16];
        attM_W  = (const float*)d_in[17];
        attM_b  = (const float*)d_in[18];
        attA_W  = (const float*)d_in[19];
        attA_b  = (const float*)d_in[20];
        attT_W  = (const float*)d_in[21];
        attT_b  = (const float*)d_in[22];
    }
    const float* a_main  = (const float*)d_in[23];
    const float* a_add   = (const float*)d_in[24];
    const float* a_trust = (const float*)d_in[25];
    const float* W1 = (const float*)d_in[26];
    const float* b1 = (const float*)d_in[27];
    const float* W2 = (const float*)d_in[28];
    const float* b2 = (const float*)d_in[29];
    const float* W3 = (const float*)d_in[30];
    const float* b3 = (const float*)d_in[31];

    float* out      = (float*)d_out;
    float* predOut  = out;
    float* userOut  = out + BB;
    float* itemOut  = out + BB + BB * D;
    float* finalOut = out + BB + 2 * BB * D;

    const int TPB = 256;
    const int SETUP_BLOCKS = (NN * D / 4 + TPB - 1) / TPB;
    const int E4_BLOCKS = (NNZ / 4 + TPB - 1) / TPB;
    const int SPMM_BLOCKS = (NN * 32 + TPB - 1) / TPB;
    const int GEMM_BLOCKS = (NN + 127) / 128;
    const int COMB_BLOCKS = 592;

    static cudaStream_t st[3];
    static cudaEvent_t evStart, evReady, evL[NLAYERS][3], evC;
    static bool inited = false;
    if (!inited) {
        for (int r = 0; r < 3; r++) cudaStreamCreateWithFlags(&st[r], cudaStreamNonBlocking);
        cudaEventCreateWithFlags(&evStart, cudaEventDisableTiming);
        cudaEventCreateWithFlags(&evReady, cudaEventDisableTiming);
        cudaEventCreateWithFlags(&evC, cudaEventDisableTiming);
        for (int l = 0; l < NLAYERS; l++)
            for (int r = 0; r < 3; r++)
                cudaEventCreateWithFlags(&evL[l][r], cudaEventDisableTiming);
        cudaFuncSetAttribute(gemm_mma_kernel, cudaFuncAttributeMaxDynamicSharedMemorySize,
                             GEMM_SMEM_BYTES);
        inited = true;
    }

    cudaEventRecord(evStart, 0);
    for (int r = 0; r < 3; r++) {
        cudaStreamWaitEvent(st[r], evStart, 0);
        hist_kernel<<<E4_BLOCKS, TPB, 0, st[r]>>>(rowP[r], r);
        scan_local_kernel<<<NB, 1024, 0, st[r]>>>(r);
        scan_blk_kernel<<<1, 128, 0, st[r]>>>(r);
        scatter_kernel<<<E4_BLOCKS, TPB, 0, st[r]>>>(rowP[r], colP[r], valP[r], r);
    }

    setup_kernel<<<SETUP_BLOCKS, TPB>>>(uEmbd, iEmbd);
    wconv_kernel<<<dim3(NLAYERS, 5), 256>>>(lin_W, inter_W, attM_W, attT_W, attA_W);
    cudaEventRecord(evReady, 0);

    for (int r = 0; r < 3; r++) {
        cudaStreamWaitEvent(st[r], evReady, 0);
        spmm_kernel<<<SPMM_BLOCKS, TPB, 0, st[r]>>>(r);
        gemm_mma_kernel<<<GEMM_BLOCKS, 256, GEMM_SMEM_BYTES, st[r]>>>(
            0, r, lin_b, inter_b, attM_b, attT_b, attA_b, a_main, a_trust, a_add);
        cudaEventRecord(evL[0][r], st[r]);
    }
    for (int r = 0; r < 3; r++) cudaStreamWaitEvent(0, evL[0][r], 0);
    combine_kernel<<<COMB_BLOCKS, 512>>>(0, finalOut);
    cudaEventRecord(evC, 0);

    for (int r = 0; r < 3; r++) {
        cudaStreamWaitEvent(st[r], evC, 0);
        spmm_kernel<<<SPMM_BLOCKS, TPB, 0, st[r]>>>(r);
        gemm_mma_kernel<<<GEMM_BLOCKS, 256, GEMM_SMEM_BYTES, st[r]>>>(
            1, r, lin_b, inter_b, attM_b, attT_b, attA_b, a_main, a_trust, a_add);
        cudaEventRecord(evL[1][r], st[r]);
    }
    for (int r = 0; r < 3; r++) cudaStreamWaitEvent(0, evL[1][r], 0);
    combine_kernel<<<COMB_BLOCKS, 512>>>(1, finalOut);

    mlp_kernel<<<BB / 4, 256>>>(userIdx, itemIdx, W1, b1, W2, b2, W3, b3,
                                finalOut, predOut, userOut, itemOut);
}

// round 15
// speedup vs baseline: 1.1057x; 1.0148x over previous
#include <cuda_runtime.h>
#include <cuda_bf16.h>
#include <cuda_fp16.h>
#include <math.h>
#include <stdint.h>

#define N_USER 60000
#define N_ITEM 40000
#define NN     100000
#define D      64
#define NNZ    1600000
#define BB     16384
#define NLAYERS 2
#define NB     98          // ceil(NN/1024)

typedef unsigned long long u64;

// ---------------- packed f32x2 helpers ----------------
__device__ __forceinline__ u64 f2dup(float v) {
    u64 r; asm("mov.b64 %0,{%1,%1};" : "=l"(r) : "f"(v)); return r;
}
__device__ __forceinline__ u64 ffma2(u64 a, u64 b, u64 c) {
    u64 d; asm("fma.rn.f32x2 %0,%1,%2,%3;" : "=l"(d) : "l"(a), "l"(b), "l"(c)); return d;
}
__device__ __forceinline__ u64 fmul2(u64 a, u64 b) {
    u64 d; asm("mul.rn.f32x2 %0,%1,%2;" : "=l"(d) : "l"(a), "l"(b)); return d;
}
__device__ __forceinline__ u64 fadd2(u64 a, u64 b) {
    u64 d; asm("add.rn.f32x2 %0,%1,%2;" : "=l"(d) : "l"(a), "l"(b)); return d;
}
__device__ __forceinline__ void funpack2(u64 v, float& lo, float& hi) {
    asm("mov.b64 {%0,%1},%2;" : "=f"(lo), "=f"(hi) : "l"(v));
}

// ---------------- mma.sync helpers ----------------
__device__ __forceinline__ uint32_t smem_to_u32(const void* p) {
    uint32_t a;
    asm("{ .reg .u64 t; cvta.to.shared.u64 t, %1; cvt.u32.u64 %0, t; }" : "=r"(a) : "l"(p));
    return a;
}
__device__ __forceinline__ void ldsm4(uint32_t* r, uint32_t addr) {
    asm volatile("ldmatrix.sync.aligned.m8n8.x4.shared.b16 {%0,%1,%2,%3}, [%4];"
        : "=r"(r[0]), "=r"(r[1]), "=r"(r[2]), "=r"(r[3]) : "r"(addr));
}
__device__ __forceinline__ uint32_t lds32(uint32_t addr) {
    uint32_t v; asm volatile("ld.shared.b32 %0, [%1];" : "=r"(v) : "r"(addr)); return v;
}
__device__ __forceinline__ void mma16816(float* d, const uint32_t* a, const uint32_t* b) {
    asm volatile(
        "mma.sync.aligned.m16n8k16.row.col.f32.bf16.bf16.f32 "
        "{%0,%1,%2,%3}, {%4,%5,%6,%7}, {%8,%9}, {%0,%1,%2,%3};"
        : "+f"(d[0]), "+f"(d[1]), "+f"(d[2]), "+f"(d[3])
        : "r"(a[0]), "r"(a[1]), "r"(a[2]), "r"(a[3]), "r"(b[0]), "r"(b[1]));
}

__device__ __forceinline__ void split2(float a, float b, uint32_t& hi, uint32_t& lo) {
    __nv_bfloat16 ah = __float2bfloat16(a);
    __nv_bfloat16 bh = __float2bfloat16(b);
    __nv_bfloat16 al = __float2bfloat16(a - __bfloat162float(ah));
    __nv_bfloat16 bl = __float2bfloat16(b - __bfloat162float(bh));
    hi = (uint32_t)__bfloat16_as_ushort(ah) | ((uint32_t)__bfloat16_as_ushort(bh) << 16);
    lo = (uint32_t)__bfloat16_as_ushort(al) | ((uint32_t)__bfloat16_as_ushort(bl) << 16);
}

#define STRD 72
#define STRDW 36

// ---------------- scratch ----------------
__device__ float    g_X[NN * D];
__device__ float    g_facc[NN * D];
__device__ uint32_t g_h12h[3][NN * 32];  // h12 as half2 per u32 (col pairs)
__device__ u64   g_A[3][NN * 32];       // packed: lo32 = (S+X) hi-split, hi32 = lo-split
__device__ u64   g_A2[3][NN * 32];      // packed S2
__device__ int   g_rowptr[3][NN + 1];   // block-LOCAL exclusive scans (+blk at use)
__device__ u64   g_edge[3][NNZ];        // hi32 = val, lo32 = col*64
__device__ int   g_count3[3][NN];       // zero-init; scan_local re-zeroes after read
__device__ int   g_cursor3[3][NN];      // block-local cursors
__device__ int   g_blk[3][128];         // per-block exclusive offsets
__device__ float g_attsum[NLAYERS][3];
__device__ uint4 g_Wpack[NLAYERS][10][576];

// ---------------- setup: zero attsums, init X ----------------
__global__ void setup_kernel(const float* __restrict__ uE, const float* __restrict__ iE) {
    int i = blockIdx.x * blockDim.x + threadIdx.x;
    if (i < NLAYERS * 3) ((float*)g_attsum)[i] = 0.f;
    if (i < NN * D / 4) {
        int j = i * 4;
        float4 v = (j < N_USER * D) ? ((const float4*)uE)[i]
                                    : ((const float4*)iE)[i - N_USER * D / 4];
        ((float4*)g_X)[i] = v;
    }
}

// ---------------- weight pre-conversion (once per launch) ----------------
__global__ void wconv_kernel(const float* __restrict__ linW, const float* __restrict__ intW,
                             const float* __restrict__ aW0, const float* __restrict__ aW1,
                             const float* __restrict__ aW2) {
    int l = blockIdx.x, m = blockIdx.y;
    const float* src = (m == 0) ? linW : (m == 1) ? intW
                      : (m == 2) ? aW0 : (m == 3) ? aW1 : aW2;
    src += l * 4096;
    unsigned short* dh = (unsigned short*)&g_Wpack[l][m * 2][0];
    unsigned short* dl = (unsigned short*)&g_Wpack[l][m * 2 + 1][0];
    for (int i = threadIdx.x; i < 4096; i += 256) {
        int k = i >> 6, n = i & 63;
        float w = src[i];
        __nv_bfloat16 h = __float2bfloat16(w);
        dh[n * STRD + k] = __bfloat16_as_ushort(h);
        dl[n * STRD + k] = __bfloat16_as_ushort(__float2bfloat16(w - __bfloat162float(h)));
    }
}

// ---------------- CSR build (per-relation) ----------------
__global__ void hist_kernel(const int* __restrict__ row, int r) {
    int e4 = blockIdx.x * blockDim.x + threadIdx.x;
    if (e4 < NNZ / 4) {
        int4 rr = ((const int4*)row)[e4];
        atomicAdd(&g_count3[r][rr.x], 1);
        atomicAdd(&g_count3[r][rr.y], 1);
        atomicAdd(&g_count3[r][rr.z], 1);
        atomicAdd(&g_count3[r][rr.w], 1);
    }
}

__global__ void scan_local_kernel(int r) {
    __shared__ int s[1024];
    int i = blockIdx.x * 1024 + threadIdx.x;
    int c = 0;
    if (i < NN) {
        c = g_count3[r][i];
        g_count3[r][i] = 0;            // reset for next graph replay
    }
    s[threadIdx.x] = c;
    __syncthreads();
    for (int off = 1; off < 1024; off <<= 1) {
        int t = (threadIdx.x >= off) ? s[threadIdx.x - off] : 0;
        __syncthreads();
        s[threadIdx.x] += t;
        __syncthreads();
    }
    if (i < NN) {
        int excl = s[threadIdx.x] - c;
        g_rowptr[r][i]  = excl;
        g_cursor3[r][i] = excl;
    }
    if (threadIdx.x == 1023) g_blk[r][blockIdx.x] = s[1023];
}

__global__ void scan_blk_kernel(int r) {
    __shared__ int s[128];
    int tid = threadIdx.x;
    int v = (tid < NB) ? g_blk[r][tid] : 0;
    s[tid] = v;
    __syncthreads();
    for (int off = 1; off < 128; off <<= 1) {
        int t = (tid >= off) ? s[tid - off] : 0;
        __syncthreads();
        s[tid] += t;
        __syncthreads();
    }
    if (tid < NB) g_blk[r][tid] = s[tid] - v;
    if (tid == NB - 1) g_rowptr[r][NN] = v;
}

__global__ void scatter_kernel(const int* __restrict__ row, const int* __restrict__ col,
                               const float* __restrict__ val, int r) {
    int e4 = blockIdx.x * blockDim.x + threadIdx.x;
    if (e4 < NNZ / 4) {
        int4   rr = ((const int4*)row)[e4];
        int4   cc = ((const int4*)col)[e4];
        float4 vv = ((const float4*)val)[e4];
        u64* __restrict__ ed = g_edge[r];
        const int* __restrict__ blk = g_blk[r];
        int p;
        p = atomicAdd(&g_cursor3[r][rr.x], 1) + blk[rr.x >> 10];
        ed[p] = ((u64)(uint32_t)__float_as_int(vv.x) << 32) | ((uint32_t)cc.x << 6);
        p = atomicAdd(&g_cursor3[r][rr.y], 1) + blk[rr.y >> 10];
        ed[p] = ((u64)(uint32_t)__float_as_int(vv.y) << 32) | ((uint32_t)cc.y << 6);
        p = atomicAdd(&g_cursor3[r][rr.z], 1) + blk[rr.z >> 10];
        ed[p] = ((u64)(uint32_t)__float_as_int(vv.z) << 32) | ((uint32_t)cc.z << 6);
        p = atomicAdd(&g_cursor3[r][rr.w], 1) + blk[rr.w >> 10];
        ed[p] = ((u64)(uint32_t)__float_as_int(vv.w) << 32) | ((uint32_t)cc.w << 6);
    }
}

// fused SpMM: A = L@X + X, A2 = L@(X*X); warp per row; 8-deep gather pipeline
__global__ void spmm_kernel(int r) {
    int gw = (blockIdx.x * blockDim.x + threadIdx.x) >> 5;
    int lane = threadIdx.x & 31;
    if (gw >= NN) return;
    const u64* __restrict__ ed = g_edge[r];
    int beg = g_rowptr[r][gw]     + g_blk[r][gw >> 10];
    int end = g_rowptr[r][gw + 1] + g_blk[r][(gw + 1) >> 10];
    u64 a = 0ull, b = 0ull;
    int e = beg;
    int l2 = 2 * lane;
    for (; e + 8 <= end; e += 8) {
        u64 p0 = ed[e],     p1 = ed[e + 1], p2 = ed[e + 2], p3 = ed[e + 3];
        u64 p4 = ed[e + 4], p5 = ed[e + 5], p6 = ed[e + 6], p7 = ed[e + 7];
        u64 x0 = *(const u64*)&g_X[(uint32_t)p0 + l2];
        u64 x1 = *(const u64*)&g_X[(uint32_t)p1 + l2];
        u64 x2 = *(const u64*)&g_X[(uint32_t)p2 + l2];
        u64 x3 = *(const u64*)&g_X[(uint32_t)p3 + l2];
        u64 x4 = *(const u64*)&g_X[(uint32_t)p4 + l2];
        u64 x5 = *(const u64*)&g_X[(uint32_t)p5 + l2];
        u64 x6 = *(const u64*)&g_X[(uint32_t)p6 + l2];
        u64 x7 = *(const u64*)&g_X[(uint32_t)p7 + l2];
        u64 v0 = f2dup(__uint_as_float((uint32_t)(p0 >> 32)));
        u64 v1 = f2dup(__uint_as_float((uint32_t)(p1 >> 32)));
        u64 v2 = f2dup(__uint_as_float((uint32_t)(p2 >> 32)));
        u64 v3 = f2dup(__uint_as_float((uint32_t)(p3 >> 32)));
        u64 v4 = f2dup(__uint_as_float((uint32_t)(p4 >> 32)));
        u64 v5 = f2dup(__uint_as_float((uint32_t)(p5 >> 32)));
        u64 v6 = f2dup(__uint_as_float((uint32_t)(p6 >> 32)));
        u64 v7 = f2dup(__uint_as_float((uint32_t)(p7 >> 32)));
        a = ffma2(v0, x0, a); b = ffma2(v0, fmul2(x0, x0), b);
        a = ffma2(v1, x1, a); b = ffma2(v1, fmul2(x1, x1), b);
        a = ffma2(v2, x2, a); b = ffma2(v2, fmul2(x2, x2), b);
        a = ffma2(v3, x3, a); b = ffma2(v3, fmul2(x3, x3), b);
        a = ffma2(v4, x4, a); b = ffma2(v4, fmul2(x4, x4), b);
        a = ffma2(v5, x5, a); b = ffma2(v5, fmul2(x5, x5), b);
        a = ffma2(v6, x6, a); b = ffma2(v6, fmul2(x6, x6), b);
        a = ffma2(v7, x7, a); b = ffma2(v7, fmul2(x7, x7), b);
    }
    for (; e < end; e++) {
        u64 p0 = ed[e];
        u64 x0 = *(const u64*)&g_X[(uint32_t)p0 + l2];
        u64 v0 = f2dup(__uint_as_float((uint32_t)(p0 >> 32)));
        a = ffma2(v0, x0, a); b = ffma2(v0, fmul2(x0, x0), b);
    }
    u64 xr = *(const u64*)&g_X[(size_t)gw * D + l2];
    a = fadd2(a, xr);

    float a0, a1, b0, b1;
    funpack2(a, a0, a1);
    funpack2(b, b0, b1);
    uint32_t hi, lo;
    size_t idx = (size_t)gw * 32 + lane;
    split2(a0, a1, hi, lo);
    g_A[r][idx]  = ((u64)lo << 32) | hi;
    split2(b0, b1, hi, lo);
    g_A2[r][idx] = ((u64)lo << 32) | hi;
}

// ---------------- HMMA GEMM (pre-converted weights, ~93 KB smem, 2 blocks/SM) ----------------
#define BUF_H  0
#define BUF_L  18432
#define OFF_WLH 36864
#define OFF_WLL 46080
#define OFF_WIH 55296
#define OFF_WIL 64512
#define OFF_WAH 73728
#define OFF_WAL 82944
#define OFF_B12 92160
#define OFF_BA  92416
#define OFF_AV  92672
#define GEMM_SMEM_BYTES 92928

__device__ __forceinline__ void stage_pair(char* smc, const u64* __restrict__ gp,
                                           int rowBase, int t) {
    uint32_t* bh = (uint32_t*)(smc + BUF_H);
    uint32_t* bl = (uint32_t*)(smc + BUF_L);
    #pragma unroll
    for (int i = t; i < 4096; i += 256) {
        int row = i >> 5, c = i & 31;
        int grow = rowBase + row;
        u64 v = 0ull;
        if (grow < NN) v = gp[(size_t)grow * 32 + c];
        bh[row * STRDW + c] = (uint32_t)v;
        bl[row * STRDW + c] = (uint32_t)(v >> 32);
    }
}

__global__ void __launch_bounds__(256) gemm_mma_kernel(
    int l, int r,
    const float* __restrict__ lin_b, const float* __restrict__ inter_b,
    const float* __restrict__ attb0, const float* __restrict__ attb1, const float* __restrict__ attb2,
    const float* __restrict__ av0,   const float* __restrict__ av1,   const float* __restrict__ av2)
{
    extern __shared__ char smc[];
    uint32_t sbase = smem_to_u32(smc);

    const float* attb = ((r == 0) ? attb0 : (r == 1) ? attb1 : attb2) + l * 64;
    const float* avec = ((r == 0) ? av0   : (r == 1) ? av1   : av2)   + l * 64;

    int t = threadIdx.x, wid = t >> 5, lane = t & 31;
    int warpRow = wid * 16;
    int rowBase = blockIdx.x * 128;

    {
        const uint4* __restrict__ wsrc = &g_Wpack[l][0][0];
        uint4* wdst = (uint4*)(smc + OFF_WLH);
        #pragma unroll 4
        for (int i = t; i < 6 * 576; i += 256) {
            int a = i / 576, o = i - a * 576;
            int ga = (a < 4) ? a : (4 + 2 * r + (a - 4));
            wdst[a * 576 + o] = wsrc[ga * 576 + o];
        }
    }
    if (t < 64) {
        ((float*)(smc + OFF_B12))[t] = lin_b[l * 64 + t] + inter_b[l * 64 + t];
        ((float*)(smc + OFF_BA))[t]  = attb[t];
        ((float*)(smc + OFF_AV))[t]  = avec[t];
    }

    stage_pair(smc, g_A[r], rowBase, t);
    __syncthreads();

    float acc[8][4];
    #pragma unroll
    for (int n = 0; n < 8; n++)
        #pragma unroll
        for (int q = 0; q < 4; q++) acc[n][q] = 0.f;

    int lr = lane & 15, kh = lane >> 4;
    int gid = lane >> 2, qk = lane & 3;

    #pragma unroll
    for (int kt = 0; kt < 4; kt++) {
        uint32_t rowoff = (uint32_t)((warpRow + lr) * STRD + kt * 16 + kh * 8) * 2;
        uint32_t aH[4], aL[4];
        ldsm4(aH, sbase + BUF_H + rowoff);
        ldsm4(aL, sbase + BUF_L + rowoff);
        #pragma unroll
        for (int nt = 0; nt < 8; nt++) {
            uint32_t wb = (uint32_t)((nt * 8 + gid) * STRD + kt * 16 + qk * 2) * 2;
            uint32_t bWLh[2], bWLl[2];
            bWLh[0] = lds32(sbase + OFF_WLH + wb); bWLh[1] = lds32(sbase + OFF_WLH + wb + 16);
            bWLl[0] = lds32(sbase + OFF_WLL + wb); bWLl[1] = lds32(sbase + OFF_WLL + wb + 16);
            mma16816(acc[nt], aH, bWLh);
            mma16816(acc[nt], aH, bWLl);
            mma16816(acc[nt], aL, bWLh);
        }
    }
    __syncthreads();

    stage_pair(smc, g_A2[r], rowBase, t);
    __syncthreads();

    #pragma unroll
    for (int kt = 0; kt < 4; kt++) {
        uint32_t rowoff = (uint32_t)((warpRow + lr) * STRD + kt * 16 + kh * 8) * 2;
        uint32_t aH[4], aL[4];
        ldsm4(aH, sbase + BUF_H + rowoff);
        ldsm4(aL, sbase + BUF_L + rowoff);
        #pragma unroll
        for (int nt = 0; nt < 8; nt++) {
            uint32_t wb = (uint32_t)((nt * 8 + gid) * STRD + kt * 16 + qk * 2) * 2;
            uint32_t bWIh[2], bWIl[2];
            bWIh[0] = lds32(sbase + OFF_WIH + wb); bWIh[1] = lds32(sbase + OFF_WIH + wb + 16);
            bWIl[0] = lds32(sbase + OFF_WIL + wb); bWIl[1] = lds32(sbase + OFF_WIL + wb + 16);
            mma16816(acc[nt], aH, bWIh);
            mma16816(acc[nt], aH, bWIl);
            mma16816(acc[nt], aL, bWIh);
        }
    }
    __syncthreads();

    const float* b12 = (const float*)(smc + OFF_B12);
    uint32_t* __restrict__ h12out = g_h12h[r];
    int row0 = rowBase + warpRow + gid;
    int row1 = row0 + 8;
    #pragma unroll
    for (int nt = 0; nt < 8; nt++) {
        int col = nt * 8 + qk * 2;
        float h00 = acc[nt][0] + b12[col], h01 = acc[nt][1] + b12[col + 1];
        float h10 = acc[nt][2] + b12[col], h11 = acc[nt][3] + b12[col + 1];
        if (row0 < NN) {
            __half2 p = __float22half2_rn(make_float2(h00, h01));
            h12out[(size_t)row0 * 32 + (col >> 1)] = *(uint32_t*)&p;
        }
        if (row1 < NN) {
            __half2 p = __float22half2_rn(make_float2(h10, h11));
            h12out[(size_t)row1 * 32 + (col >> 1)] = *(uint32_t*)&p;
        }
        uint32_t hi, lo;
        uint32_t so0 = (uint32_t)((warpRow + gid) * STRD + col) * 2;
        uint32_t so1 = (uint32_t)((warpRow + gid + 8) * STRD + col) * 2;
        split2(h00, h01, hi, lo);
        *(uint32_t*)(smc + BUF_H + so0) = hi;
        *(uint32_t*)(smc + BUF_L + so0) = lo;
        split2(h10, h11, hi, lo);
        *(uint32_t*)(smc + BUF_H + so1) = hi;
        *(uint32_t*)(smc + BUF_L + so1) = lo;
    }
    __syncwarp();

    float zac[8][4];
    #pragma unroll
    for (int n = 0; n < 8; n++)
        #pragma unroll
        for (int q = 0; q < 4; q++) zac[n][q] = 0.f;

    #pragma unroll
    for (int kt = 0; kt < 4; kt++) {
        uint32_t rowoff = (uint32_t)((warpRow + lr) * STRD + kt * 16 + kh * 8) * 2;
        uint32_t hH[4], hL[4];
        ldsm4(hH, sbase + BUF_H + rowoff);
        ldsm4(hL, sbase + BUF_L + rowoff);
        #pragma unroll
        for (int nt = 0; nt < 8; nt++) {
            uint32_t wb = (uint32_t)((nt * 8 + gid) * STRD + kt * 16 + qk * 2) * 2;
            uint32_t bWAh[2], bWAl[2];
            bWAh[0] = lds32(sbase + OFF_WAH + wb); bWAh[1] = lds32(sbase + OFF_WAH + wb + 16);
            bWAl[0] = lds32(sbase + OFF_WAL + wb); bWAl[1] = lds32(sbase + OFF_WAL + wb + 16);
            mma16816(zac[nt], hH, bWAh);
            mma16816(zac[nt], hH, bWAl);
            mma16816(zac[nt], hL, bWAh);
        }
    }

    const float* bA = (const float*)(smc + OFF_BA);
    const float* aV = (const float*)(smc + OFF_AV);
    float attLocal = 0.f;
    bool v0 = row0 < NN, v1 = row1 < NN;
    #pragma unroll
    for (int nt = 0; nt < 8; nt++) {
        int col = nt * 8 + qk * 2;
        float avc0 = aV[col], avc1 = aV[col + 1];
        float bc0 = bA[col], bc1 = bA[col + 1];
        if (v0) attLocal += tanhf(zac[nt][0] + bc0) * avc0 + tanhf(zac[nt][1] + bc1) * avc1;
        if (v1) attLocal += tanhf(zac[nt][2] + bc0) * avc0 + tanhf(zac[nt][3] + bc1) * avc1;
    }
    #pragma unroll
    for (int off = 16; off; off >>= 1)
        attLocal += __shfl_down_sync(0xffffffffu, attLocal, off);
    if (lane == 0) atomicAdd(&g_attsum[l][r], attLocal);
}

// ---------------- combine (+ fused beta softmax; l0 derives facc from X_old) -----
__global__ void __launch_bounds__(512) combine_kernel(int l, float* __restrict__ finalOut) {
    __shared__ float betas[3];
    if (threadIdx.x == 0) {
        float m = g_attsum[l][0] / (float)NN;
        float t = g_attsum[l][1] / (float)NN;
        float a = g_attsum[l][2] / (float)NN;
        float mx = fmaxf(m, fmaxf(a, t));
        float e0 = expf(m - mx), e1 = expf(a - mx), e2 = expf(t - mx);
        float s = e0 + e1 + e2;
        betas[0] = e0 / s;
        betas[1] = e2 / s;
        betas[2] = e1 / s;
    }
    __syncthreads();
    float b0 = betas[0], b1 = betas[1], b2 = betas[2];
    const u64* __restrict__ H0 = (const u64*)g_h12h[0];
    const u64* __restrict__ H1 = (const u64*)g_h12h[1];
    const u64* __restrict__ H2 = (const u64*)g_h12h[2];
    for (int i = blockIdx.x * blockDim.x + threadIdx.x; i < NN * D / 4;
         i += gridDim.x * blockDim.x) {
        u64 q0 = H0[i], q1 = H1[i], q2 = H2[i];
        float2 a0 = __half22float2(*(__half2*)&q0);
        float2 a1 = __half22float2(*((__half2*)&q0 + 1));
        float2 c0 = __half22float2(*(__half2*)&q1);
        float2 c1 = __half22float2(*((__half2*)&q1 + 1));
        float2 d0 = __half22float2(*(__half2*)&q2);
        float2 d1 = __half22float2(*((__half2*)&q2 + 1));
        float4 v;
        v.x = b0 * a0.x + b1 * c0.x + b2 * d0.x;
        v.y = b0 * a0.y + b1 * c0.y + b2 * d0.y;
        v.z = b0 * a1.x + b1 * c1.x + b2 * d1.x;
        v.w = b0 * a1.y + b1 * c1.y + b2 * d1.y;
        if (l == 0) {
            float4 x = ((const float4*)g_X)[i];
            float4 f;
            f.x = x.x + v.x; f.y = x.y + v.y; f.z = x.z + v.z; f.w = x.w + v.w;
            ((float4*)g_facc)[i] = f;
            ((float4*)g_X)[i] = v;
        } else {
            float4 f = ((const float4*)g_facc)[i];
            const float k = 1.0f / 3.0f;
            v.x = (f.x + v.x) * k;
            v.y = (f.y + v.y) * k;
            v.z = (f.z + v.z) * k;
            v.w = (f.w + v.w) * k;
            ((float4*)finalOut)[i] = v;
        }
    }
}

// 4 pairs per 256-thread block
__global__ void __launch_bounds__(256) mlp_kernel(
    const int* __restrict__ userIdx, const int* __restrict__ itemIdx,
    const float* __restrict__ W1, const float* __restrict__ b1,
    const float* __restrict__ W2, const float* __restrict__ b2,
    const float* __restrict__ W3, const float* __restrict__ b3,
    const float* __restrict__ finalE,
    float* __restrict__ pred, float* __restrict__ outU, float* __restrict__ outI)
{
    __shared__ float h[4][128];
    __shared__ float h1s[4][64];
    __shared__ float h2s[4][32];
    int g = threadIdx.x >> 6;
    int t = threadIdx.x & 63;
    int bI = blockIdx.x * 4 + g;
    int u = userIdx[bI];
    int v = itemIdx[bI] + N_USER;
    float fu = finalE[(size_t)u * D + t];
    float fi = finalE[(size_t)v * D + t];
    h[g][t] = fu; h[g][64 + t] = fi;
    outU[(size_t)bI * D + t] = fu;
    outI[(size_t)bI * D + t] = fi;
    __syncthreads();

    float acc = b1[t];
    #pragma unroll 16
    for (int k = 0; k < 128; k++) acc += h[g][k] * W1[k * 64 + t];
    h1s[g][t] = fmaxf(acc, 0.f);
    __syncthreads();

    if (t < 32) {
        float a2 = b2[t];
        #pragma unroll 16
        for (int k = 0; k < 64; k++) a2 += h1s[g][k] * W2[k * 32 + t];
        h2s[g][t] = a2;
    }
    __syncthreads();
    if (t < 32) {
        float p = h2s[g][t] * W3[t];
        #pragma unroll
        for (int off = 16; off; off >>= 1) p += __shfl_down_sync(0xffffffffu, p, off);
        if (t == 0) pred[bI] = p + b3[0];
    }
}

// ---------------- launch ----------------
extern "C" void kernel_launch(void* const* d_in, const int* in_sizes, int n_in,
                              void* d_out, int out_size)
{
    const int*   userIdx = (const int*)d_in[0];
    const int*   itemIdx = (const int*)d_in[1];
    const float* uEmbd   = (const float*)d_in[2];
    const float* iEmbd   = (const float*)d_in[3];

    const int*   rowP[3] = { (const int*)d_in[4],  (const int*)d_in[7],  (const int*)d_in[10] };
    const int*   colP[3] = { (const int*)d_in[5],  (const int*)d_in[8],  (const int*)d_in[11] };
    const float* valP[3] = { (const float*)d_in[6], (const float*)d_in[9], (const float*)d_in[12] };

    const float *lin_W, *lin_b, *inter_W, *inter_b;
    const float *attM_W, *attM_b, *attA_W, *attA_b, *attT_W, *attT_b;
    if (in_sizes[14] == 2 * D * D) {
        lin_W   = (const float*)d_in[13];
        inter_W = (const float*)d_in[14];
        attM_W  = (const float*)d_in[15];
        attA_W  = (const float*)d_in[16];
        attT_W  = (const float*)d_in[17];
        lin_b   = (const float*)d_in[18];
        inter_b = (const float*)d_in[19];
        attM_b  = (const float*)d_in[20];
        attA_b  = (const float*)d_in[21];
        attT_b  = (const float*)d_in[22];
    } else {
        lin_W   = (const float*)d_in[13];
        lin_b   = (const float*)d_in[14];
        inter_W = (const float*)d_in[15];
        inter_b = (const float*)d_in[16];
        attM_W  = (const float*)d_in[17];
        attM_b  = (const float*)d_in[18];
        attA_W  = (const float*)d_in[19];
        attA_b  = (const float*)d_in[20];
        attT_W  = (const float*)d_in[21];
        attT_b  = (const float*)d_in[22];
    }
    const float* a_main  = (const float*)d_in[23];
    const float* a_add   = (const float*)d_in[24];
    const float* a_trust = (const float*)d_in[25];
    const float* W1 = (const float*)d_in[26];
    const float* b1 = (const float*)d_in[27];
    const float* W2 = (const float*)d_in[28];
    const float* b2 = (const float*)d_in[29];
    const float* W3 = (const float*)d_in[30];
    const float* b3 = (const float*)d_in[31];

    float* out      = (float*)d_out;
    float* predOut  = out;
    float* userOut  = out + BB;
    float* itemOut  = out + BB + BB * D;
    float* finalOut = out + BB + 2 * BB * D;

    const int TPB = 256;
    const int SETUP_BLOCKS = (NN * D / 4 + TPB - 1) / TPB;
    const int E4_BLOCKS = (NNZ / 4 + TPB - 1) / TPB;
    const int SPMM_BLOCKS = (NN * 32 + TPB - 1) / TPB;
    const int GEMM_BLOCKS = (NN + 127) / 128;
    const int COMB_BLOCKS = 592;

    static cudaStream_t st[3];
    static cudaEvent_t evStart, evReady, evL[NLAYERS][3], evC;
    static bool inited = false;
    if (!inited) {
        for (int r = 0; r < 3; r++) cudaStreamCreateWithFlags(&st[r], cudaStreamNonBlocking);
        cudaEventCreateWithFlags(&evStart, cudaEventDisableTiming);
        cudaEventCreateWithFlags(&evReady, cudaEventDisableTiming);
        cudaEventCreateWithFlags(&evC, cudaEventDisableTiming);
        for (int l = 0; l < NLAYERS; l++)
            for (int r = 0; r < 3; r++)
                cudaEventCreateWithFlags(&evL[l][r], cudaEventDisableTiming);
        cudaFuncSetAttribute(gemm_mma_kernel, cudaFuncAttributeMaxDynamicSharedMemorySize,
                             GEMM_SMEM_BYTES);
        inited = true;
    }

    cudaEventRecord(evStart, 0);
    for (int r = 0; r < 3; r++) {
        cudaStreamWaitEvent(st[r], evStart, 0);
        hist_kernel<<<E4_BLOCKS, TPB, 0, st[r]>>>(rowP[r], r);
        scan_local_kernel<<<NB, 1024, 0, st[r]>>>(r);
        scan_blk_kernel<<<1, 128, 0, st[r]>>>(r);
        scatter_kernel<<<E4_BLOCKS, TPB, 0, st[r]>>>(rowP[r], colP[r], valP[r], r);
    }

    setup_kernel<<<SETUP_BLOCKS, TPB>>>(uEmbd, iEmbd);
    wconv_kernel<<<dim3(NLAYERS, 5), 256>>>(lin_W, inter_W, attM_W, attT_W, attA_W);
    cudaEventRecord(evReady, 0);

    for (int r = 0; r < 3; r++) {
        cudaStreamWaitEvent(st[r], evReady, 0);
        spmm_kernel<<<SPMM_BLOCKS, TPB, 0, st[r]>>>(r);
        gemm_mma_kernel<<<GEMM_BLOCKS, 256, GEMM_SMEM_BYTES, st[r]>>>(
            0, r, lin_b, inter_b, attM_b, attT_b, attA_b, a_main, a_trust, a_add);
        cudaEventRecord(evL[0][r], st[r]);
    }
    for (int r = 0; r < 3; r++) cudaStreamWaitEvent(0, evL[0][r], 0);
    combine_kernel<<<COMB_BLOCKS, 512>>>(0, finalOut);
    cudaEventRecord(evC, 0);

    for (int r = 0; r < 3; r++) {
        cudaStreamWaitEvent(st[r], evC, 0);
        spmm_kernel<<<SPMM_BLOCKS, TPB, 0, st[r]>>>(r);
        gemm_mma_kernel<<<GEMM_BLOCKS, 256, GEMM_SMEM_BYTES, st[r]>>>(
            1, r, lin_b, inter_b, attM_b, attT_b, attA_b, a_main, a_trust, a_add);
        cudaEventRecord(evL[1][r], st[r]);
    }
    for (int r = 0; r < 3; r++) cudaStreamWaitEvent(0, evL[1][r], 0);
    combine_kernel<<<COMB_BLOCKS, 512>>>(1, finalOut);

    mlp_kernel<<<BB / 4, 256>>>(userIdx, itemIdx, W1, b1, W2, b2, W3, b3,
                                finalOut, predOut, userOut, itemOut);
}

// round 16
// speedup vs baseline: 1.1201x; 1.0131x over previous
#include <cuda_runtime.h>
#include <cuda_bf16.h>
#include <cuda_fp16.h>
#include <math.h>
#include <stdint.h>

#define N_USER 60000
#define N_ITEM 40000
#define NN     100000
#define D      64
#define NNZ    1600000
#define BB     16384
#define NLAYERS 2
#define NB     98          // ceil(NN/1024)

typedef unsigned long long u64;

// ---------------- packed f32x2 helpers ----------------
__device__ __forceinline__ u64 f2dup(float v) {
    u64 r; asm("mov.b64 %0,{%1,%1};" : "=l"(r) : "f"(v)); return r;
}
__device__ __forceinline__ u64 ffma2(u64 a, u64 b, u64 c) {
    u64 d; asm("fma.rn.f32x2 %0,%1,%2,%3;" : "=l"(d) : "l"(a), "l"(b), "l"(c)); return d;
}
__device__ __forceinline__ u64 fmul2(u64 a, u64 b) {
    u64 d; asm("mul.rn.f32x2 %0,%1,%2;" : "=l"(d) : "l"(a), "l"(b)); return d;
}
__device__ __forceinline__ u64 fadd2(u64 a, u64 b) {
    u64 d; asm("add.rn.f32x2 %0,%1,%2;" : "=l"(d) : "l"(a), "l"(b)); return d;
}
__device__ __forceinline__ void funpack2(u64 v, float& lo, float& hi) {
    asm("mov.b64 {%0,%1},%2;" : "=f"(lo), "=f"(hi) : "l"(v));
}

// ---------------- mma.sync helpers ----------------
__device__ __forceinline__ uint32_t smem_to_u32(const void* p) {
    uint32_t a;
    asm("{ .reg .u64 t; cvta.to.shared.u64 t, %1; cvt.u32.u64 %0, t; }" : "=r"(a) : "l"(p));
    return a;
}
__device__ __forceinline__ void ldsm4(uint32_t* r, uint32_t addr) {
    asm volatile("ldmatrix.sync.aligned.m8n8.x4.shared.b16 {%0,%1,%2,%3}, [%4];"
        : "=r"(r[0]), "=r"(r[1]), "=r"(r[2]), "=r"(r[3]) : "r"(addr));
}
__device__ __forceinline__ uint32_t lds32(uint32_t addr) {
    uint32_t v; asm volatile("ld.shared.b32 %0, [%1];" : "=r"(v) : "r"(addr)); return v;
}
__device__ __forceinline__ void mma16816(float* d, const uint32_t* a, const uint32_t* b) {
    asm volatile(
        "mma.sync.aligned.m16n8k16.row.col.f32.bf16.bf16.f32 "
        "{%0,%1,%2,%3}, {%4,%5,%6,%7}, {%8,%9}, {%0,%1,%2,%3};"
        : "+f"(d[0]), "+f"(d[1]), "+f"(d[2]), "+f"(d[3])
        : "r"(a[0]), "r"(a[1]), "r"(a[2]), "r"(a[3]), "r"(b[0]), "r"(b[1]));
}

__device__ __forceinline__ void split2(float a, float b, uint32_t& hi, uint32_t& lo) {
    __nv_bfloat16 ah = __float2bfloat16(a);
    __nv_bfloat16 bh = __float2bfloat16(b);
    __nv_bfloat16 al = __float2bfloat16(a - __bfloat162float(ah));
    __nv_bfloat16 bl = __float2bfloat16(b - __bfloat162float(bh));
    hi = (uint32_t)__bfloat16_as_ushort(ah) | ((uint32_t)__bfloat16_as_ushort(bh) << 16);
    lo = (uint32_t)__bfloat16_as_ushort(al) | ((uint32_t)__bfloat16_as_ushort(bl) << 16);
}

#define STRD 72
#define STRDW 36

// ---------------- scratch ----------------
__device__ float    g_X[NN * D];         // layer-1 output (layer-2 gather source)
__device__ float    g_facc[NN * D];
__device__ uint32_t g_h12h[3][NN * 32];  // h12 as half2 per u32 (col pairs)
__device__ u64   g_A[3][NN * 32];        // packed bf16 hi/lo splits
__device__ u64   g_A2[3][NN * 32];
__device__ int   g_rowptr[3][NN + 1];    // block-LOCAL exclusive scans (+blk at use)
__device__ u64   g_edge[3][NNZ];         // hi32 = val, lo32 = col*64
__device__ int   g_count3[3][NN];        // zero-init; scan_local re-zeroes after read
__device__ int   g_cursor3[3][NN];
__device__ int   g_blk[3][128];
__device__ float g_attsum[NLAYERS][3];
__device__ uint4 g_Wpack[NLAYERS][10][576];

// ---------------- setup: zero attsums only (X no longer staged) ----------------
__global__ void setup_kernel() {
    if (threadIdx.x < NLAYERS * 3) ((float*)g_attsum)[threadIdx.x] = 0.f;
}

// ---------------- weight pre-conversion (once per launch) ----------------
__global__ void wconv_kernel(const float* __restrict__ linW, const float* __restrict__ intW,
                             const float* __restrict__ aW0, const float* __restrict__ aW1,
                             const float* __restrict__ aW2) {
    int l = blockIdx.x, m = blockIdx.y;
    const float* src = (m == 0) ? linW : (m == 1) ? intW
                      : (m == 2) ? aW0 : (m == 3) ? aW1 : aW2;
    src += l * 4096;
    unsigned short* dh = (unsigned short*)&g_Wpack[l][m * 2][0];
    unsigned short* dl = (unsigned short*)&g_Wpack[l][m * 2 + 1][0];
    for (int i = threadIdx.x; i < 4096; i += 256) {
        int k = i >> 6, n = i & 63;
        float w = src[i];
        __nv_bfloat16 h = __float2bfloat16(w);
        dh[n * STRD + k] = __bfloat16_as_ushort(h);
        dl[n * STRD + k] = __bfloat16_as_ushort(__float2bfloat16(w - __bfloat162float(h)));
    }
}

// ---------------- CSR build (per-relation) ----------------
__global__ void hist_kernel(const int* __restrict__ row, int r) {
    int e4 = blockIdx.x * blockDim.x + threadIdx.x;
    if (e4 < NNZ / 4) {
        int4 rr = ((const int4*)row)[e4];
        atomicAdd(&g_count3[r][rr.x], 1);
        atomicAdd(&g_count3[r][rr.y], 1);
        atomicAdd(&g_count3[r][rr.z], 1);
        atomicAdd(&g_count3[r][rr.w], 1);
    }
}

__global__ void scan_local_kernel(int r) {
    __shared__ int s[1024];
    int i = blockIdx.x * 1024 + threadIdx.x;
    int c = 0;
    if (i < NN) {
        c = g_count3[r][i];
        g_count3[r][i] = 0;            // reset for next graph replay
    }
    s[threadIdx.x] = c;
    __syncthreads();
    for (int off = 1; off < 1024; off <<= 1) {
        int t = (threadIdx.x >= off) ? s[threadIdx.x - off] : 0;
        __syncthreads();
        s[threadIdx.x] += t;
        __syncthreads();
    }
    if (i < NN) {
        int excl = s[threadIdx.x] - c;
        g_rowptr[r][i]  = excl;
        g_cursor3[r][i] = excl;
    }
    if (threadIdx.x == 1023) g_blk[r][blockIdx.x] = s[1023];
}

__global__ void scan_blk_kernel(int r) {
    __shared__ int s[128];
    int tid = threadIdx.x;
    int v = (tid < NB) ? g_blk[r][tid] : 0;
    s[tid] = v;
    __syncthreads();
    for (int off = 1; off < 128; off <<= 1) {
        int t = (tid >= off) ? s[tid - off] : 0;
        __syncthreads();
        s[tid] += t;
        __syncthreads();
    }
    if (tid < NB) g_blk[r][tid] = s[tid] - v;
    if (tid == NB - 1) g_rowptr[r][NN] = v;
}

__global__ void scatter_kernel(const int* __restrict__ row, const int* __restrict__ col,
                               const float* __restrict__ val, int r) {
    int e4 = blockIdx.x * blockDim.x + threadIdx.x;
    if (e4 < NNZ / 4) {
        int4   rr = ((const int4*)row)[e4];
        int4   cc = ((const int4*)col)[e4];
        float4 vv = ((const float4*)val)[e4];
        u64* __restrict__ ed = g_edge[r];
        const int* __restrict__ blk = g_blk[r];
        int p;
        p = atomicAdd(&g_cursor3[r][rr.x], 1) + blk[rr.x >> 10];
        ed[p] = ((u64)(uint32_t)__float_as_int(vv.x) << 32) | ((uint32_t)cc.x << 6);
        p = atomicAdd(&g_cursor3[r][rr.y], 1) + blk[rr.y >> 10];
        ed[p] = ((u64)(uint32_t)__float_as_int(vv.y) << 32) | ((uint32_t)cc.y << 6);
        p = atomicAdd(&g_cursor3[r][rr.z], 1) + blk[rr.z >> 10];
        ed[p] = ((u64)(uint32_t)__float_as_int(vv.z) << 32) | ((uint32_t)cc.z << 6);
        p = atomicAdd(&g_cursor3[r][rr.w], 1) + blk[rr.w >> 10];
        ed[p] = ((u64)(uint32_t)__float_as_int(vv.w) << 32) | ((uint32_t)cc.w << 6);
    }
}

// fused SpMM: A = L@X + X, A2 = L@(X*X); warp per row; 8-deep gather pipeline.
// Gathers from (baseA | baseB) split at `thresh` (scaled index). Layer 0 passes
// uE / (iE - thresh) so embeddings are read in place; layer 1 passes g_X / g_X.
__global__ void spmm_kernel(int r, const float* __restrict__ baseA,
                            const float* __restrict__ baseB, int thresh) {
    int gw = (blockIdx.x * blockDim.x + threadIdx.x) >> 5;
    int lane = threadIdx.x & 31;
    if (gw >= NN) return;
    const u64* __restrict__ ed = g_edge[r];
    int beg = g_rowptr[r][gw]     + g_blk[r][gw >> 10];
    int end = g_rowptr[r][gw + 1] + g_blk[r][(gw + 1) >> 10];
    u64 a = 0ull, b = 0ull;
    int e = beg;
    int l2 = 2 * lane;

    #define GATHER(p) (*(const u64*)&(((int)(uint32_t)(p) < thresh) ? baseA : baseB)[(uint32_t)(p) + l2])

    for (; e + 8 <= end; e += 8) {
        u64 p0 = ed[e],     p1 = ed[e + 1], p2 = ed[e + 2], p3 = ed[e + 3];
        u64 p4 = ed[e + 4], p5 = ed[e + 5], p6 = ed[e + 6], p7 = ed[e + 7];
        u64 x0 = GATHER(p0);
        u64 x1 = GATHER(p1);
        u64 x2 = GATHER(p2);
        u64 x3 = GATHER(p3);
        u64 x4 = GATHER(p4);
        u64 x5 = GATHER(p5);
        u64 x6 = GATHER(p6);
        u64 x7 = GATHER(p7);
        u64 v0 = f2dup(__uint_as_float((uint32_t)(p0 >> 32)));
        u64 v1 = f2dup(__uint_as_float((uint32_t)(p1 >> 32)));
        u64 v2 = f2dup(__uint_as_float((uint32_t)(p2 >> 32)));
        u64 v3 = f2dup(__uint_as_float((uint32_t)(p3 >> 32)));
        u64 v4 = f2dup(__uint_as_float((uint32_t)(p4 >> 32)));
        u64 v5 = f2dup(__uint_as_float((uint32_t)(p5 >> 32)));
        u64 v6 = f2dup(__uint_as_float((uint32_t)(p6 >> 32)));
        u64 v7 = f2dup(__uint_as_float((uint32_t)(p7 >> 32)));
        a = ffma2(v0, x0, a); b = ffma2(v0, fmul2(x0, x0), b);
        a = ffma2(v1, x1, a); b = ffma2(v1, fmul2(x1, x1), b);
        a = ffma2(v2, x2, a); b = ffma2(v2, fmul2(x2, x2), b);
        a = ffma2(v3, x3, a); b = ffma2(v3, fmul2(x3, x3), b);
        a = ffma2(v4, x4, a); b = ffma2(v4, fmul2(x4, x4), b);
        a = ffma2(v5, x5, a); b = ffma2(v5, fmul2(x5, x5), b);
        a = ffma2(v6, x6, a); b = ffma2(v6, fmul2(x6, x6), b);
        a = ffma2(v7, x7, a); b = ffma2(v7, fmul2(x7, x7), b);
    }
    for (; e < end; e++) {
        u64 p0 = ed[e];
        u64 x0 = GATHER(p0);
        u64 v0 = f2dup(__uint_as_float((uint32_t)(p0 >> 32)));
        a = ffma2(v0, x0, a); b = ffma2(v0, fmul2(x0, x0), b);
    }
    // + X identity term for this row
    {
        uint32_t ro = (uint32_t)gw * D;
        u64 xr = GATHER(ro);
        a = fadd2(a, xr);
    }
    #undef GATHER

    float a0, a1, b0, b1;
    funpack2(a, a0, a1);
    funpack2(b, b0, b1);
    uint32_t hi, lo;
    size_t idx = (size_t)gw * 32 + lane;
    split2(a0, a1, hi, lo);
    g_A[r][idx]  = ((u64)lo << 32) | hi;
    split2(b0, b1, hi, lo);
    g_A2[r][idx] = ((u64)lo << 32) | hi;
}

// ---------------- HMMA GEMM (pre-converted weights, ~93 KB smem, 2 blocks/SM) ----------------
#define BUF_H  0
#define BUF_L  18432
#define OFF_WLH 36864
#define OFF_WLL 46080
#define OFF_WIH 55296
#define OFF_WIL 64512
#define OFF_WAH 73728
#define OFF_WAL 82944
#define OFF_B12 92160
#define OFF_BA  92416
#define OFF_AV  92672
#define GEMM_SMEM_BYTES 92928

__device__ __forceinline__ void stage_pair(char* smc, const u64* __restrict__ gp,
                                           int rowBase, int t) {
    uint32_t* bh = (uint32_t*)(smc + BUF_H);
    uint32_t* bl = (uint32_t*)(smc + BUF_L);
    #pragma unroll
    for (int i = t; i < 4096; i += 256) {
        int row = i >> 5, c = i & 31;
        int grow = rowBase + row;
        u64 v = 0ull;
        if (grow < NN) v = gp[(size_t)grow * 32 + c];
        bh[row * STRDW + c] = (uint32_t)v;
        bl[row * STRDW + c] = (uint32_t)(v >> 32);
    }
}

__global__ void __launch_bounds__(256) gemm_mma_kernel(
    int l, int r,
    const float* __restrict__ lin_b, const float* __restrict__ inter_b,
    const float* __restrict__ attb0, const float* __restrict__ attb1, const float* __restrict__ attb2,
    const float* __restrict__ av0,   const float* __restrict__ av1,   const float* __restrict__ av2)
{
    extern __shared__ char smc[];
    uint32_t sbase = smem_to_u32(smc);

    const float* attb = ((r == 0) ? attb0 : (r == 1) ? attb1 : attb2) + l * 64;
    const float* avec = ((r == 0) ? av0   : (r == 1) ? av1   : av2)   + l * 64;

    int t = threadIdx.x, wid = t >> 5, lane = t & 31;
    int warpRow = wid * 16;
    int rowBase = blockIdx.x * 128;

    {
        const uint4* __restrict__ wsrc = &g_Wpack[l][0][0];
        uint4* wdst = (uint4*)(smc + OFF_WLH);
        #pragma unroll 4
        for (int i = t; i < 6 * 576; i += 256) {
            int a = i / 576, o = i - a * 576;
            int ga = (a < 4) ? a : (4 + 2 * r + (a - 4));
            wdst[a * 576 + o] = wsrc[ga * 576 + o];
        }
    }
    if (t < 64) {
        ((float*)(smc + OFF_B12))[t] = lin_b[l * 64 + t] + inter_b[l * 64 + t];
        ((float*)(smc + OFF_BA))[t]  = attb[t];
        ((float*)(smc + OFF_AV))[t]  = avec[t];
    }

    stage_pair(smc, g_A[r], rowBase, t);
    __syncthreads();

    float acc[8][4];
    #pragma unroll
    for (int n = 0; n < 8; n++)
        #pragma unroll
        for (int q = 0; q < 4; q++) acc[n][q] = 0.f;

    int lr = lane & 15, kh = lane >> 4;
    int gid = lane >> 2, qk = lane & 3;

    #pragma unroll
    for (int kt = 0; kt < 4; kt++) {
        uint32_t rowoff = (uint32_t)((warpRow + lr) * STRD + kt * 16 + kh * 8) * 2;
        uint32_t aH[4], aL[4];
        ldsm4(aH, sbase + BUF_H + rowoff);
        ldsm4(aL, sbase + BUF_L + rowoff);
        #pragma unroll
        for (int nt = 0; nt < 8; nt++) {
            uint32_t wb = (uint32_t)((nt * 8 + gid) * STRD + kt * 16 + qk * 2) * 2;
            uint32_t bWLh[2], bWLl[2];
            bWLh[0] = lds32(sbase + OFF_WLH + wb); bWLh[1] = lds32(sbase + OFF_WLH + wb + 16);
            bWLl[0] = lds32(sbase + OFF_WLL + wb); bWLl[1] = lds32(sbase + OFF_WLL + wb + 16);
            mma16816(acc[nt], aH, bWLh);
            mma16816(acc[nt], aH, bWLl);
            mma16816(acc[nt], aL, bWLh);
        }
    }
    __syncthreads();

    stage_pair(smc, g_A2[r], rowBase, t);
    __syncthreads();

    #pragma unroll
    for (int kt = 0; kt < 4; kt++) {
        uint32_t rowoff = (uint32_t)((warpRow + lr) * STRD + kt * 16 + kh * 8) * 2;
        uint32_t aH[4], aL[4];
        ldsm4(aH, sbase + BUF_H + rowoff);
        ldsm4(aL, sbase + BUF_L + rowoff);
        #pragma unroll
        for (int nt = 0; nt < 8; nt++) {
            uint32_t wb = (uint32_t)((nt * 8 + gid) * STRD + kt * 16 + qk * 2) * 2;
            uint32_t bWIh[2], bWIl[2];
            bWIh[0] = lds32(sbase + OFF_WIH + wb); bWIh[1] = lds32(sbase + OFF_WIH + wb + 16);
            bWIl[0] = lds32(sbase + OFF_WIL + wb); bWIl[1] = lds32(sbase + OFF_WIL + wb + 16);
            mma16816(acc[nt], aH, bWIh);
            mma16816(acc[nt], aH, bWIl);
            mma16816(acc[nt], aL, bWIh);
        }
    }
    __syncthreads();

    const float* b12 = (const float*)(smc + OFF_B12);
    uint32_t* __restrict__ h12out = g_h12h[r];
    int row0 = rowBase + warpRow + gid;
    int row1 = row0 + 8;
    #pragma unroll
    for (int nt = 0; nt < 8; nt++) {
        int col = nt * 8 + qk * 2;
        float h00 = acc[nt][0] + b12[col], h01 = acc[nt][1] + b12[col + 1];
        float h10 = acc[nt][2] + b12[col], h11 = acc[nt][3] + b12[col + 1];
        if (row0 < NN) {
            __half2 p = __float22half2_rn(make_float2(h00, h01));
            h12out[(size_t)row0 * 32 + (col >> 1)] = *(uint32_t*)&p;
        }
        if (row1 < NN) {
            __half2 p = __float22half2_rn(make_float2(h10, h11));
            h12out[(size_t)row1 * 32 + (col >> 1)] = *(uint32_t*)&p;
        }
        uint32_t hi, lo;
        uint32_t so0 = (uint32_t)((warpRow + gid) * STRD + col) * 2;
        uint32_t so1 = (uint32_t)((warpRow + gid + 8) * STRD + col) * 2;
        split2(h00, h01, hi, lo);
        *(uint32_t*)(smc + BUF_H + so0) = hi;
        *(uint32_t*)(smc + BUF_L + so0) = lo;
        split2(h10, h11, hi, lo);
        *(uint32_t*)(smc + BUF_H + so1) = hi;
        *(uint32_t*)(smc + BUF_L + so1) = lo;
    }
    __syncwarp();

    float zac[8][4];
    #pragma unroll
    for (int n = 0; n < 8; n++)
        #pragma unroll
        for (int q = 0; q < 4; q++) zac[n][q] = 0.f;

    #pragma unroll
    for (int kt = 0; kt < 4; kt++) {
        uint32_t rowoff = (uint32_t)((warpRow + lr) * STRD + kt * 16 + kh * 8) * 2;
        uint32_t hH[4], hL[4];
        ldsm4(hH, sbase + BUF_H + rowoff);
        ldsm4(hL, sbase + BUF_L + rowoff);
        #pragma unroll
        for (int nt = 0; nt < 8; nt++) {
            uint32_t wb = (uint32_t)((nt * 8 + gid) * STRD + kt * 16 + qk * 2) * 2;
            uint32_t bWAh[2], bWAl[2];
            bWAh[0] = lds32(sbase + OFF_WAH + wb); bWAh[1] = lds32(sbase + OFF_WAH + wb + 16);
            bWAl[0] = lds32(sbase + OFF_WAL + wb); bWAl[1] = lds32(sbase + OFF_WAL + wb + 16);
            mma16816(zac[nt], hH, bWAh);
            mma16816(zac[nt], hH, bWAl);
            mma16816(zac[nt], hL, bWAh);
        }
    }

    const float* bA = (const float*)(smc + OFF_BA);
    const float* aV = (const float*)(smc + OFF_AV);
    float attLocal = 0.f;
    bool v0 = row0 < NN, v1 = row1 < NN;
    #pragma unroll
    for (int nt = 0; nt < 8; nt++) {
        int col = nt * 8 + qk * 2;
        float avc0 = aV[col], avc1 = aV[col + 1];
        float bc0 = bA[col], bc1 = bA[col + 1];
        if (v0) attLocal += tanhf(zac[nt][0] + bc0) * avc0 + tanhf(zac[nt][1] + bc1) * avc1;
        if (v1) attLocal += tanhf(zac[nt][2] + bc0) * avc0 + tanhf(zac[nt][3] + bc1) * avc1;
    }
    #pragma unroll
    for (int off = 16; off; off >>= 1)
        attLocal += __shfl_down_sync(0xffffffffu, attLocal, off);
    if (lane == 0) atomicAdd(&g_attsum[l][r], attLocal);
}

// ---------------- combine (+ fused beta softmax) ----------------
// l0: facc = embeddings + v ; X = v       l1: finalOut = (facc + v) / 3
__global__ void __launch_bounds__(512) combine_kernel(
    int l, float* __restrict__ finalOut,
    const float* __restrict__ uE, const float* __restrict__ iE)
{
    __shared__ float betas[3];
    if (threadIdx.x == 0) {
        float m = g_attsum[l][0] / (float)NN;
        float t = g_attsum[l][1] / (float)NN;
        float a = g_attsum[l][2] / (float)NN;
        float mx = fmaxf(m, fmaxf(a, t));
        float e0 = expf(m - mx), e1 = expf(a - mx), e2 = expf(t - mx);
        float s = e0 + e1 + e2;
        betas[0] = e0 / s;
        betas[1] = e2 / s;
        betas[2] = e1 / s;
    }
    __syncthreads();
    float b0 = betas[0], b1 = betas[1], b2 = betas[2];
    const u64* __restrict__ H0 = (const u64*)g_h12h[0];
    const u64* __restrict__ H1 = (const u64*)g_h12h[1];
    const u64* __restrict__ H2 = (const u64*)g_h12h[2];
    for (int i = blockIdx.x * blockDim.x + threadIdx.x; i < NN * D / 4;
         i += gridDim.x * blockDim.x) {
        u64 q0 = H0[i], q1 = H1[i], q2 = H2[i];
        float2 a0 = __half22float2(*(__half2*)&q0);
        float2 a1 = __half22float2(*((__half2*)&q0 + 1));
        float2 c0 = __half22float2(*(__half2*)&q1);
        float2 c1 = __half22float2(*((__half2*)&q1 + 1));
        float2 d0 = __half22float2(*(__half2*)&q2);
        float2 d1 = __half22float2(*((__half2*)&q2 + 1));
        float4 v;
        v.x = b0 * a0.x + b1 * c0.x + b2 * d0.x;
        v.y = b0 * a0.y + b1 * c0.y + b2 * d0.y;
        v.z = b0 * a1.x + b1 * c1.x + b2 * d1.x;
        v.w = b0 * a1.y + b1 * c1.y + b2 * d1.y;
        if (l == 0) {
            int j = i * 4;
            float4 x = (j < N_USER * D) ? ((const float4*)uE)[i]
                                        : ((const float4*)iE)[i - N_USER * D / 4];
            float4 f;
            f.x = x.x + v.x; f.y = x.y + v.y; f.z = x.z + v.z; f.w = x.w + v.w;
            ((float4*)g_facc)[i] = f;
            ((float4*)g_X)[i] = v;
        } else {
            float4 f = ((const float4*)g_facc)[i];
            const float k = 1.0f / 3.0f;
            v.x = (f.x + v.x) * k;
            v.y = (f.y + v.y) * k;
            v.z = (f.z + v.z) * k;
            v.w = (f.w + v.w) * k;
            ((float4*)finalOut)[i] = v;
        }
    }
}

// 4 pairs per 256-thread block
__global__ void __launch_bounds__(256) mlp_kernel(
    const int* __restrict__ userIdx, const int* __restrict__ itemIdx,
    const float* __restrict__ W1, const float* __restrict__ b1,
    const float* __restrict__ W2, const float* __restrict__ b2,
    const float* __restrict__ W3, const float* __restrict__ b3,
    const float* __restrict__ finalE,
    float* __restrict__ pred, float* __restrict__ outU, float* __restrict__ outI)
{
    __shared__ float h[4][128];
    __shared__ float h1s[4][64];
    __shared__ float h2s[4][32];
    int g = threadIdx.x >> 6;
    int t = threadIdx.x & 63;
    int bI = blockIdx.x * 4 + g;
    int u = userIdx[bI];
    int v = itemIdx[bI] + N_USER;
    float fu = finalE[(size_t)u * D + t];
    float fi = finalE[(size_t)v * D + t];
    h[g][t] = fu; h[g][64 + t] = fi;
    outU[(size_t)bI * D + t] = fu;
    outI[(size_t)bI * D + t] = fi;
    __syncthreads();

    float acc = b1[t];
    #pragma unroll 16
    for (int k = 0; k < 128; k++) acc += h[g][k] * W1[k * 64 + t];
    h1s[g][t] = fmaxf(acc, 0.f);
    __syncthreads();

    if (t < 32) {
        float a2 = b2[t];
        #pragma unroll 16
        for (int k = 0; k < 64; k++) a2 += h1s[g][k] * W2[k * 32 + t];
        h2s[g][t] = a2;
    }
    __syncthreads();
    if (t < 32) {
        float p = h2s[g][t] * W3[t];
        #pragma unroll
        for (int off = 16; off; off >>= 1) p += __shfl_down_sync(0xffffffffu, p, off);
        if (t == 0) pred[bI] = p + b3[0];
    }
}

// ---------------- launch ----------------
extern "C" void kernel_launch(void* const* d_in, const int* in_sizes, int n_in,
                              void* d_out, int out_size)
{
    const int*   userIdx = (const int*)d_in[0];
    const int*   itemIdx = (const int*)d_in[1];
    const float* uEmbd   = (const float*)d_in[2];
    const float* iEmbd   = (const float*)d_in[3];

    const int*   rowP[3] = { (const int*)d_in[4],  (const int*)d_in[7],  (const int*)d_in[10] };
    const int*   colP[3] = { (const int*)d_in[5],  (const int*)d_in[8],  (const int*)d_in[11] };
    const float* valP[3] = { (const float*)d_in[6], (const float*)d_in[9], (const float*)d_in[12] };

    const float *lin_W, *lin_b, *inter_W, *inter_b;
    const float *attM_W, *attM_b, *attA_W, *attA_b, *attT_W, *attT_b;
    if (in_sizes[14] == 2 * D * D) {
        lin_W   = (const float*)d_in[13];
        inter_W = (const float*)d_in[14];
        attM_W  = (const float*)d_in[15];
        attA_W  = (const float*)d_in[16];
        attT_W  = (const float*)d_in[17];
        lin_b   = (const float*)d_in[18];
        inter_b = (const float*)d_in[19];
        attM_b  = (const float*)d_in[20];
        attA_b  = (const float*)d_in[21];
        attT_b  = (const float*)d_in[22];
    } else {
        lin_W   = (const float*)d_in[13];
        lin_b   = (const float*)d_in[14];
        inter_W = (const float*)d_in[15];
        inter_b = (const float*)d_in[16];
        attM_W  = (const float*)d_in[17];
        attM_b  = (const float*)d_in[18];
        attA_W  = (const float*)d_in[19];
        attA_b  = (const float*)d_in[20];
        attT_W  = (const float*)d_in[21];
        attT_b  = (const float*)d_in[22];
    }
    const float* a_main  = (const float*)d_in[23];
    const float* a_add   = (const float*)d_in[24];
    const float* a_trust = (const float*)d_in[25];
    const float* W1 = (const float*)d_in[26];
    const float* b1 = (const float*)d_in[27];
    const float* W2 = (const float*)d_in[28];
    const float* b2 = (const float*)d_in[29];
    const float* W3 = (const float*)d_in[30];
    const float* b3 = (const float*)d_in[31];

    float* out      = (float*)d_out;
    float* predOut  = out;
    float* userOut  = out + BB;
    float* itemOut  = out + BB + BB * D;
    float* finalOut = out + BB + 2 * BB * D;

    const int TPB = 256;
    const int E4_BLOCKS = (NNZ / 4 + TPB - 1) / TPB;
    const int SPMM_BLOCKS = (NN * 32 + TPB - 1) / TPB;
    const int GEMM_BLOCKS = (NN + 127) / 128;
    const int COMB_BLOCKS = 592;

    // layer-0 gather: baseA = uEmbd for scaled idx < N_USER*D, baseB adjusted iEmbd
    const float* iAdj = iEmbd - (size_t)N_USER * D;   // pointer math only; never deref < thresh
    const int THRESH0 = N_USER * D;

    // layer-1 gather: g_X via device symbol address
    static float* xPtr = nullptr;
    static cudaStream_t st[3];
    static cudaEvent_t evStart, evReady, evL[NLAYERS][3], evC;
    static bool inited = false;
    if (!inited) {
        cudaGetSymbolAddress((void**)&xPtr, g_X);
        for (int r = 0; r < 3; r++) cudaStreamCreateWithFlags(&st[r], cudaStreamNonBlocking);
        cudaEventCreateWithFlags(&evStart, cudaEventDisableTiming);
        cudaEventCreateWithFlags(&evReady, cudaEventDisableTiming);
        cudaEventCreateWithFlags(&evC, cudaEventDisableTiming);
        for (int l = 0; l < NLAYERS; l++)
            for (int r = 0; r < 3; r++)
                cudaEventCreateWithFlags(&evL[l][r], cudaEventDisableTiming);
        cudaFuncSetAttribute(gemm_mma_kernel, cudaFuncAttributeMaxDynamicSharedMemorySize,
                             GEMM_SMEM_BYTES);
        inited = true;
    }

    cudaEventRecord(evStart, 0);
    for (int r = 0; r < 3; r++) {
        cudaStreamWaitEvent(st[r], evStart, 0);
        hist_kernel<<<E4_BLOCKS, TPB, 0, st[r]>>>(rowP[r], r);
        scan_local_kernel<<<NB, 1024, 0, st[r]>>>(r);
        scan_blk_kernel<<<1, 128, 0, st[r]>>>(r);
        scatter_kernel<<<E4_BLOCKS, TPB, 0, st[r]>>>(rowP[r], colP[r], valP[r], r);
        // layer-0 spmm reads embeddings directly: no dependency on origin stream
        spmm_kernel<<<SPMM_BLOCKS, TPB, 0, st[r]>>>(r, uEmbd, iAdj, THRESH0);
    }

    // concurrent with CSR build + layer-0 spmm
    setup_kernel<<<1, 32>>>();
    wconv_kernel<<<dim3(NLAYERS, 5), 256>>>(lin_W, inter_W, attM_W, attT_W, attA_W);
    cudaEventRecord(evReady, 0);

    for (int r = 0; r < 3; r++) {
        cudaStreamWaitEvent(st[r], evReady, 0);   // gemm needs Wpack + zeroed attsum
        gemm_mma_kernel<<<GEMM_BLOCKS, 256, GEMM_SMEM_BYTES, st[r]>>>(
            0, r, lin_b, inter_b, attM_b, attT_b, attA_b, a_main, a_trust, a_add);
        cudaEventRecord(evL[0][r], st[r]);
    }
    for (int r = 0; r < 3; r++) cudaStreamWaitEvent(0, evL[0][r], 0);
    combine_kernel<<<COMB_BLOCKS, 512>>>(0, finalOut, uEmbd, iEmbd);
    cudaEventRecord(evC, 0);

    for (int r = 0; r < 3; r++) {
        cudaStreamWaitEvent(st[r], evC, 0);
        spmm_kernel<<<SPMM_BLOCKS, TPB, 0, st[r]>>>(r, xPtr, xPtr, 0x7fffffff);
        gemm_mma_kernel<<<GEMM_BLOCKS, 256, GEMM_SMEM_BYTES, st[r]>>>(
            1, r, lin_b, inter_b, attM_b, attT_b, attA_b, a_main, a_trust, a_add);
        cudaEventRecord(evL[1][r], st[r]);
    }
    for (int r = 0; r < 3; r++) cudaStreamWaitEvent(0, evL[1][r], 0);
    combine_kernel<<<COMB_BLOCKS, 512>>>(1, finalOut, uEmbd, iEmbd);

    mlp_kernel<<<BB / 4, 256>>>(userIdx, itemIdx, W1, b1, W2, b2, W3, b3,
                                finalOut, predOut, userOut, itemOut);
}

// round 17
// speedup vs baseline: 1.1943x; 1.0663x over previous
#include <cuda_runtime.h>
#include <cuda_bf16.h>
#include <cuda_fp16.h>
#include <math.h>
#include <stdint.h>

#define N_USER 60000
#define N_ITEM 40000
#define NN     100000
#define D      64
#define NNZ    1600000
#define BB     16384
#define NLAYERS 2
#define NB     98          // ceil(NN/1024)

typedef unsigned long long u64;

// ---------------- packed f32x2 helpers ----------------
__device__ __forceinline__ u64 f2dup(float v) {
    u64 r; asm("mov.b64 %0,{%1,%1};" : "=l"(r) : "f"(v)); return r;
}
__device__ __forceinline__ u64 ffma2(u64 a, u64 b, u64 c) {
    u64 d; asm("fma.rn.f32x2 %0,%1,%2,%3;" : "=l"(d) : "l"(a), "l"(b), "l"(c)); return d;
}
__device__ __forceinline__ u64 fmul2(u64 a, u64 b) {
    u64 d; asm("mul.rn.f32x2 %0,%1,%2;" : "=l"(d) : "l"(a), "l"(b)); return d;
}
__device__ __forceinline__ u64 fadd2(u64 a, u64 b) {
    u64 d; asm("add.rn.f32x2 %0,%1,%2;" : "=l"(d) : "l"(a), "l"(b)); return d;
}
__device__ __forceinline__ void funpack2(u64 v, float& lo, float& hi) {
    asm("mov.b64 {%0,%1},%2;" : "=f"(lo), "=f"(hi) : "l"(v));
}

// ---------------- mma.sync helpers ----------------
__device__ __forceinline__ uint32_t smem_to_u32(const void* p) {
    uint32_t a;
    asm("{ .reg .u64 t; cvta.to.shared.u64 t, %1; cvt.u32.u64 %0, t; }" : "=r"(a) : "l"(p));
    return a;
}
__device__ __forceinline__ void ldsm4(uint32_t* r, uint32_t addr) {
    asm volatile("ldmatrix.sync.aligned.m8n8.x4.shared.b16 {%0,%1,%2,%3}, [%4];"
        : "=r"(r[0]), "=r"(r[1]), "=r"(r[2]), "=r"(r[3]) : "r"(addr));
}
__device__ __forceinline__ uint32_t lds32(uint32_t addr) {
    uint32_t v; asm volatile("ld.shared.b32 %0, [%1];" : "=r"(v) : "r"(addr)); return v;
}
__device__ __forceinline__ void mma16816(float* d, const uint32_t* a, const uint32_t* b) {
    asm volatile(
        "mma.sync.aligned.m16n8k16.row.col.f32.bf16.bf16.f32 "
        "{%0,%1,%2,%3}, {%4,%5,%6,%7}, {%8,%9}, {%0,%1,%2,%3};"
        : "+f"(d[0]), "+f"(d[1]), "+f"(d[2]), "+f"(d[3])
        : "r"(a[0]), "r"(a[1]), "r"(a[2]), "r"(a[3]), "r"(b[0]), "r"(b[1]));
}

__device__ __forceinline__ void split2(float a, float b, uint32_t& hi, uint32_t& lo) {
    __nv_bfloat16 ah = __float2bfloat16(a);
    __nv_bfloat16 bh = __float2bfloat16(b);
    __nv_bfloat16 al = __float2bfloat16(a - __bfloat162float(ah));
    __nv_bfloat16 bl = __float2bfloat16(b - __bfloat162float(bh));
    hi = (uint32_t)__bfloat16_as_ushort(ah) | ((uint32_t)__bfloat16_as_ushort(bh) << 16);
    lo = (uint32_t)__bfloat16_as_ushort(al) | ((uint32_t)__bfloat16_as_ushort(bl) << 16);
}

#define STRD 72
#define STRDW 36

// ---------------- scratch ----------------
__device__ float    g_X[NN * D];         // layer-1 output (layer-2 gather source)
__device__ float    g_facc[NN * D];
__device__ uint32_t g_h12h[3][NN * 32];  // h12 as half2 per u32 (col pairs)
__device__ u64   g_A[3][NN * 32];        // packed bf16 hi/lo splits
__device__ u64   g_A2[3][NN * 32];
__device__ int   g_rowptr[3][NN + 1];    // block-LOCAL exclusive scans (+blk at use)
__device__ u64   g_edge[3][NNZ];         // hi32 = val, lo32 = col*64
__device__ int   g_count3[3][NN];        // zero-init; scan_local re-zeroes after read
__device__ int   g_cursor3[3][NN];
__device__ int   g_blk[3][128];
__device__ float g_attsum[NLAYERS][3];
__device__ uint4 g_Wpack[NLAYERS][10][576];

// ---------------- setup: zero attsums only ----------------
__global__ void setup_kernel() {
    if (threadIdx.x < NLAYERS * 3) ((float*)g_attsum)[threadIdx.x] = 0.f;
}

// ---------------- weight pre-conversion (once per launch) ----------------
__global__ void wconv_kernel(const float* __restrict__ linW, const float* __restrict__ intW,
                             const float* __restrict__ aW0, const float* __restrict__ aW1,
                             const float* __restrict__ aW2) {
    int l = blockIdx.x, m = blockIdx.y;
    const float* src = (m == 0) ? linW : (m == 1) ? intW
                      : (m == 2) ? aW0 : (m == 3) ? aW1 : aW2;
    src += l * 4096;
    unsigned short* dh = (unsigned short*)&g_Wpack[l][m * 2][0];
    unsigned short* dl = (unsigned short*)&g_Wpack[l][m * 2 + 1][0];
    for (int i = threadIdx.x; i < 4096; i += 256) {
        int k = i >> 6, n = i & 63;
        float w = src[i];
        __nv_bfloat16 h = __float2bfloat16(w);
        dh[n * STRD + k] = __bfloat16_as_ushort(h);
        dl[n * STRD + k] = __bfloat16_as_ushort(__float2bfloat16(w - __bfloat162float(h)));
    }
}

// ---------------- CSR build (per-relation) ----------------
__global__ void hist_kernel(const int* __restrict__ row, int r) {
    int e4 = blockIdx.x * blockDim.x + threadIdx.x;
    if (e4 < NNZ / 4) {
        int4 rr = ((const int4*)row)[e4];
        atomicAdd(&g_count3[r][rr.x], 1);
        atomicAdd(&g_count3[r][rr.y], 1);
        atomicAdd(&g_count3[r][rr.z], 1);
        atomicAdd(&g_count3[r][rr.w], 1);
    }
}

__global__ void scan_local_kernel(int r) {
    __shared__ int s[1024];
    int i = blockIdx.x * 1024 + threadIdx.x;
    int c = 0;
    if (i < NN) {
        c = g_count3[r][i];
        g_count3[r][i] = 0;            // reset for next graph replay
    }
    s[threadIdx.x] = c;
    __syncthreads();
    for (int off = 1; off < 1024; off <<= 1) {
        int t = (threadIdx.x >= off) ? s[threadIdx.x - off] : 0;
        __syncthreads();
        s[threadIdx.x] += t;
        __syncthreads();
    }
    if (i < NN) {
        int excl = s[threadIdx.x] - c;
        g_rowptr[r][i]  = excl;
        g_cursor3[r][i] = excl;
    }
    if (threadIdx.x == 1023) g_blk[r][blockIdx.x] = s[1023];
}

__global__ void scan_blk_kernel(int r) {
    __shared__ int s[128];
    int tid = threadIdx.x;
    int v = (tid < NB) ? g_blk[r][tid] : 0;
    s[tid] = v;
    __syncthreads();
    for (int off = 1; off < 128; off <<= 1) {
        int t = (tid >= off) ? s[tid - off] : 0;
        __syncthreads();
        s[tid] += t;
        __syncthreads();
    }
    if (tid < NB) g_blk[r][tid] = s[tid] - v;
    if (tid == NB - 1) g_rowptr[r][NN] = v;
}

__global__ void scatter_kernel(const int* __restrict__ row, const int* __restrict__ col,
                               const float* __restrict__ val, int r) {
    int e4 = blockIdx.x * blockDim.x + threadIdx.x;
    if (e4 < NNZ / 4) {
        int4   rr = ((const int4*)row)[e4];
        int4   cc = ((const int4*)col)[e4];
        float4 vv = ((const float4*)val)[e4];
        u64* __restrict__ ed = g_edge[r];
        const int* __restrict__ blk = g_blk[r];
        int p;
        p = atomicAdd(&g_cursor3[r][rr.x], 1) + blk[rr.x >> 10];
        ed[p] = ((u64)(uint32_t)__float_as_int(vv.x) << 32) | ((uint32_t)cc.x << 6);
        p = atomicAdd(&g_cursor3[r][rr.y], 1) + blk[rr.y >> 10];
        ed[p] = ((u64)(uint32_t)__float_as_int(vv.y) << 32) | ((uint32_t)cc.y << 6);
        p = atomicAdd(&g_cursor3[r][rr.z], 1) + blk[rr.z >> 10];
        ed[p] = ((u64)(uint32_t)__float_as_int(vv.z) << 32) | ((uint32_t)cc.z << 6);
        p = atomicAdd(&g_cursor3[r][rr.w], 1) + blk[rr.w >> 10];
        ed[p] = ((u64)(uint32_t)__float_as_int(vv.w) << 32) | ((uint32_t)cc.w << 6);
    }
}

// fused SpMM: A = L@X + X, A2 = L@(X*X).
// 16 lanes per row (2 rows/warp), float4(=ulonglong2) per lane: each gather is
// one LDG.128; per-warp LDG count halves at equal bytes, rows-in-flight doubles.
__global__ void spmm_kernel(int r, const float* __restrict__ baseA,
                            const float* __restrict__ baseB, int thresh) {
    int gw = (blockIdx.x * blockDim.x + threadIdx.x) >> 4;   // row per 16 lanes
    int sl = threadIdx.x & 15;
    if (gw >= NN) return;
    const u64* __restrict__ ed = g_edge[r];
    int beg = g_rowptr[r][gw]     + g_blk[r][gw >> 10];
    int end = g_rowptr[r][gw + 1] + g_blk[r][(gw + 1) >> 10];
    u64 a0 = 0ull, a1 = 0ull, b0 = 0ull, b1 = 0ull;
    int e = beg;
    int l4 = 4 * sl;                                         // float offset in row

    #define GATH(p) (*(const ulonglong2*)&(((int)(uint32_t)(p) < thresh) ? baseA : baseB)[(uint32_t)(p) + l4])

    for (; e + 8 <= end; e += 8) {
        u64 p0 = ed[e],     p1 = ed[e + 1], p2 = ed[e + 2], p3 = ed[e + 3];
        u64 p4 = ed[e + 4], p5 = ed[e + 5], p6 = ed[e + 6], p7 = ed[e + 7];
        ulonglong2 q0 = GATH(p0);
        ulonglong2 q1 = GATH(p1);
        ulonglong2 q2 = GATH(p2);
        ulonglong2 q3 = GATH(p3);
        ulonglong2 q4 = GATH(p4);
        ulonglong2 q5 = GATH(p5);
        ulonglong2 q6 = GATH(p6);
        ulonglong2 q7 = GATH(p7);
        u64 v0 = f2dup(__uint_as_float((uint32_t)(p0 >> 32)));
        u64 v1 = f2dup(__uint_as_float((uint32_t)(p1 >> 32)));
        u64 v2 = f2dup(__uint_as_float((uint32_t)(p2 >> 32)));
        u64 v3 = f2dup(__uint_as_float((uint32_t)(p3 >> 32)));
        u64 v4 = f2dup(__uint_as_float((uint32_t)(p4 >> 32)));
        u64 v5 = f2dup(__uint_as_float((uint32_t)(p5 >> 32)));
        u64 v6 = f2dup(__uint_as_float((uint32_t)(p6 >> 32)));
        u64 v7 = f2dup(__uint_as_float((uint32_t)(p7 >> 32)));
        a0 = ffma2(v0, q0.x, a0); a1 = ffma2(v0, q0.y, a1);
        b0 = ffma2(v0, fmul2(q0.x, q0.x), b0); b1 = ffma2(v0, fmul2(q0.y, q0.y), b1);
        a0 = ffma2(v1, q1.x, a0); a1 = ffma2(v1, q1.y, a1);
        b0 = ffma2(v1, fmul2(q1.x, q1.x), b0); b1 = ffma2(v1, fmul2(q1.y, q1.y), b1);
        a0 = ffma2(v2, q2.x, a0); a1 = ffma2(v2, q2.y, a1);
        b0 = ffma2(v2, fmul2(q2.x, q2.x), b0); b1 = ffma2(v2, fmul2(q2.y, q2.y), b1);
        a0 = ffma2(v3, q3.x, a0); a1 = ffma2(v3, q3.y, a1);
        b0 = ffma2(v3, fmul2(q3.x, q3.x), b0); b1 = ffma2(v3, fmul2(q3.y, q3.y), b1);
        a0 = ffma2(v4, q4.x, a0); a1 = ffma2(v4, q4.y, a1);
        b0 = ffma2(v4, fmul2(q4.x, q4.x), b0); b1 = ffma2(v4, fmul2(q4.y, q4.y), b1);
        a0 = ffma2(v5, q5.x, a0); a1 = ffma2(v5, q5.y, a1);
        b0 = ffma2(v5, fmul2(q5.x, q5.x), b0); b1 = ffma2(v5, fmul2(q5.y, q5.y), b1);
        a0 = ffma2(v6, q6.x, a0); a1 = ffma2(v6, q6.y, a1);
        b0 = ffma2(v6, fmul2(q6.x, q6.x), b0); b1 = ffma2(v6, fmul2(q6.y, q6.y), b1);
        a0 = ffma2(v7, q7.x, a0); a1 = ffma2(v7, q7.y, a1);
        b0 = ffma2(v7, fmul2(q7.x, q7.x), b0); b1 = ffma2(v7, fmul2(q7.y, q7.y), b1);
    }
    for (; e < end; e++) {
        u64 p0 = ed[e];
        ulonglong2 q0 = GATH(p0);
        u64 v0 = f2dup(__uint_as_float((uint32_t)(p0 >> 32)));
        a0 = ffma2(v0, q0.x, a0); a1 = ffma2(v0, q0.y, a1);
        b0 = ffma2(v0, fmul2(q0.x, q0.x), b0); b1 = ffma2(v0, fmul2(q0.y, q0.y), b1);
    }
    // + X identity term
    {
        uint32_t ro = (uint32_t)gw * D;
        ulonglong2 xr = GATH(ro);
        a0 = fadd2(a0, xr.x);
        a1 = fadd2(a1, xr.y);
    }
    #undef GATH

    float f0, f1, f2, f3;
    uint32_t hi, lo;
    ulonglong2 packA, packB;
    funpack2(a0, f0, f1);
    funpack2(a1, f2, f3);
    split2(f0, f1, hi, lo); packA.x = ((u64)lo << 32) | hi;
    split2(f2, f3, hi, lo); packA.y = ((u64)lo << 32) | hi;
    funpack2(b0, f0, f1);
    funpack2(b1, f2, f3);
    split2(f0, f1, hi, lo); packB.x = ((u64)lo << 32) | hi;
    split2(f2, f3, hi, lo); packB.y = ((u64)lo << 32) | hi;
    size_t idx = (size_t)gw * 32 + 2 * sl;
    *(ulonglong2*)&g_A[r][idx]  = packA;
    *(ulonglong2*)&g_A2[r][idx] = packB;
}

// ---------------- HMMA GEMM (pre-converted weights, ~93 KB smem, 2 blocks/SM) ----------------
#define BUF_H  0
#define BUF_L  18432
#define OFF_WLH 36864
#define OFF_WLL 46080
#define OFF_WIH 55296
#define OFF_WIL 64512
#define OFF_WAH 73728
#define OFF_WAL 82944
#define OFF_B12 92160
#define OFF_BA  92416
#define OFF_AV  92672
#define GEMM_SMEM_BYTES 92928

__device__ __forceinline__ void stage_pair(char* smc, const u64* __restrict__ gp,
                                           int rowBase, int t) {
    uint32_t* bh = (uint32_t*)(smc + BUF_H);
    uint32_t* bl = (uint32_t*)(smc + BUF_L);
    #pragma unroll
    for (int i = t; i < 2048; i += 256) {
        int row = i >> 4, c = (i & 15) * 2;
        int grow = rowBase + row;
        ulonglong2 v = make_ulonglong2(0ull, 0ull);
        if (grow < NN) v = *(const ulonglong2*)&gp[(size_t)grow * 32 + c];
        bh[row * STRDW + c]     = (uint32_t)v.x;
        bl[row * STRDW + c]     = (uint32_t)(v.x >> 32);
        bh[row * STRDW + c + 1] = (uint32_t)v.y;
        bl[row * STRDW + c + 1] = (uint32_t)(v.y >> 32);
    }
}

__global__ void __launch_bounds__(256) gemm_mma_kernel(
    int l, int r,
    const float* __restrict__ lin_b, const float* __restrict__ inter_b,
    const float* __restrict__ attb0, const float* __restrict__ attb1, const float* __restrict__ attb2,
    const float* __restrict__ av0,   const float* __restrict__ av1,   const float* __restrict__ av2)
{
    extern __shared__ char smc[];
    uint32_t sbase = smem_to_u32(smc);

    const float* attb = ((r == 0) ? attb0 : (r == 1) ? attb1 : attb2) + l * 64;
    const float* avec = ((r == 0) ? av0   : (r == 1) ? av1   : av2)   + l * 64;

    int t = threadIdx.x, wid = t >> 5, lane = t & 31;
    int warpRow = wid * 16;
    int rowBase = blockIdx.x * 128;

    {
        const uint4* __restrict__ wsrc = &g_Wpack[l][0][0];
        uint4* wdst = (uint4*)(smc + OFF_WLH);
        #pragma unroll 4
        for (int i = t; i < 6 * 576; i += 256) {
            int a = i / 576, o = i - a * 576;
            int ga = (a < 4) ? a : (4 + 2 * r + (a - 4));
            wdst[a * 576 + o] = wsrc[ga * 576 + o];
        }
    }
    if (t < 64) {
        ((float*)(smc + OFF_B12))[t] = lin_b[l * 64 + t] + inter_b[l * 64 + t];
        ((float*)(smc + OFF_BA))[t]  = attb[t];
        ((float*)(smc + OFF_AV))[t]  = avec[t];
    }

    stage_pair(smc, g_A[r], rowBase, t);
    __syncthreads();

    float acc[8][4];
    #pragma unroll
    for (int n = 0; n < 8; n++)
        #pragma unroll
        for (int q = 0; q < 4; q++) acc[n][q] = 0.f;

    int lr = lane & 15, kh = lane >> 4;
    int gid = lane >> 2, qk = lane & 3;

    #pragma unroll
    for (int kt = 0; kt < 4; kt++) {
        uint32_t rowoff = (uint32_t)((warpRow + lr) * STRD + kt * 16 + kh * 8) * 2;
        uint32_t aH[4], aL[4];
        ldsm4(aH, sbase + BUF_H + rowoff);
        ldsm4(aL, sbase + BUF_L + rowoff);
        #pragma unroll
        for (int nt = 0; nt < 8; nt++) {
            uint32_t wb = (uint32_t)((nt * 8 + gid) * STRD + kt * 16 + qk * 2) * 2;
            uint32_t bWLh[2], bWLl[2];
            bWLh[0] = lds32(sbase + OFF_WLH + wb); bWLh[1] = lds32(sbase + OFF_WLH + wb + 16);
            bWLl[0] = lds32(sbase + OFF_WLL + wb); bWLl[1] = lds32(sbase + OFF_WLL + wb + 16);
            mma16816(acc[nt], aH, bWLh);
            mma16816(acc[nt], aH, bWLl);
            mma16816(acc[nt], aL, bWLh);
        }
    }
    __syncthreads();

    stage_pair(smc, g_A2[r], rowBase, t);
    __syncthreads();

    #pragma unroll
    for (int kt = 0; kt < 4; kt++) {
        uint32_t rowoff = (uint32_t)((warpRow + lr) * STRD + kt * 16 + kh * 8) * 2;
        uint32_t aH[4], aL[4];
        ldsm4(aH, sbase + BUF_H + rowoff);
        ldsm4(aL, sbase + BUF_L + rowoff);
        #pragma unroll
        for (int nt = 0; nt < 8; nt++) {
            uint32_t wb = (uint32_t)((nt * 8 + gid) * STRD + kt * 16 + qk * 2) * 2;
            uint32_t bWIh[2], bWIl[2];
            bWIh[0] = lds32(sbase + OFF_WIH + wb); bWIh[1] = lds32(sbase + OFF_WIH + wb + 16);
            bWIl[0] = lds32(sbase + OFF_WIL + wb); bWIl[1] = lds32(sbase + OFF_WIL + wb + 16);
            mma16816(acc[nt], aH, bWIh);
            mma16816(acc[nt], aH, bWIl);
            mma16816(acc[nt], aL, bWIh);
        }
    }
    __syncthreads();

    const float* b12 = (const float*)(smc + OFF_B12);
    uint32_t* __restrict__ h12out = g_h12h[r];
    int row0 = rowBase + warpRow + gid;
    int row1 = row0 + 8;
    #pragma unroll
    for (int nt = 0; nt < 8; nt++) {
        int col = nt * 8 + qk * 2;
        float h00 = acc[nt][0] + b12[col], h01 = acc[nt][1] + b12[col + 1];
        float h10 = acc[nt][2] + b12[col], h11 = acc[nt][3] + b12[col + 1];
        if (row0 < NN) {
            __half2 p = __float22half2_rn(make_float2(h00, h01));
            h12out[(size_t)row0 * 32 + (col >> 1)] = *(uint32_t*)&p;
        }
        if (row1 < NN) {
            __half2 p = __float22half2_rn(make_float2(h10, h11));
            h12out[(size_t)row1 * 32 + (col >> 1)] = *(uint32_t*)&p;
        }
        uint32_t hi, lo;
        uint32_t so0 = (uint32_t)((warpRow + gid) * STRD + col) * 2;
        uint32_t so1 = (uint32_t)((warpRow + gid + 8) * STRD + col) * 2;
        split2(h00, h01, hi, lo);
        *(uint32_t*)(smc + BUF_H + so0) = hi;
        *(uint32_t*)(smc + BUF_L + so0) = lo;
        split2(h10, h11, hi, lo);
        *(uint32_t*)(smc + BUF_H + so1) = hi;
        *(uint32_t*)(smc + BUF_L + so1) = lo;
    }
    __syncwarp();

    float zac[8][4];
    #pragma unroll
    for (int n = 0; n < 8; n++)
        #pragma unroll
        for (int q = 0; q < 4; q++) zac[n][q] = 0.f;

    #pragma unroll
    for (int kt = 0; kt < 4; kt++) {
        uint32_t rowoff = (uint32_t)((warpRow + lr) * STRD + kt * 16 + kh * 8) * 2;
        uint32_t hH[4], hL[4];
        ldsm4(hH, sbase + BUF_H + rowoff);
        ldsm4(hL, sbase + BUF_L + rowoff);
        #pragma unroll
        for (int nt = 0; nt < 8; nt++) {
            uint32_t wb = (uint32_t)((nt * 8 + gid) * STRD + kt * 16 + qk * 2) * 2;
            uint32_t bWAh[2], bWAl[2];
            bWAh[0] = lds32(sbase + OFF_WAH + wb); bWAh[1] = lds32(sbase + OFF_WAH + wb + 16);
            bWAl[0] = lds32(sbase + OFF_WAL + wb); bWAl[1] = lds32(sbase + OFF_WAL + wb + 16);
            mma16816(zac[nt], hH, bWAh);
            mma16816(zac[nt], hH, bWAl);
            mma16816(zac[nt], hL, bWAh);
        }
    }

    const float* bA = (const float*)(smc + OFF_BA);
    const float* aV = (const float*)(smc + OFF_AV);
    float attLocal = 0.f;
    bool v0 = row0 < NN, v1 = row1 < NN;
    #pragma unroll
    for (int nt = 0; nt < 8; nt++) {
        int col = nt * 8 + qk * 2;
        float avc0 = aV[col], avc1 = aV[col + 1];
        float bc0 = bA[col], bc1 = bA[col + 1];
        if (v0) attLocal += tanhf(zac[nt][0] + bc0) * avc0 + tanhf(zac[nt][1] + bc1) * avc1;
        if (v1) attLocal += tanhf(zac[nt][2] + bc0) * avc0 + tanhf(zac[nt][3] + bc1) * avc1;
    }
    #pragma unroll
    for (int off = 16; off; off >>= 1)
        attLocal += __shfl_down_sync(0xffffffffu, attLocal, off);
    if (lane == 0) atomicAdd(&g_attsum[l][r], attLocal);
}

// ---------------- combine (+ fused beta softmax) ----------------
__global__ void __launch_bounds__(512) combine_kernel(
    int l, float* __restrict__ finalOut,
    const float* __restrict__ uE, const float* __restrict__ iE)
{
    __shared__ float betas[3];
    if (threadIdx.x == 0) {
        float m = g_attsum[l][0] / (float)NN;
        float t = g_attsum[l][1] / (float)NN;
        float a = g_attsum[l][2] / (float)NN;
        float mx = fmaxf(m, fmaxf(a, t));
        float e0 = expf(m - mx), e1 = expf(a - mx), e2 = expf(t - mx);
        float s = e0 + e1 + e2;
        betas[0] = e0 / s;
        betas[1] = e2 / s;
        betas[2] = e1 / s;
    }
    __syncthreads();
    float b0 = betas[0], b1 = betas[1], b2 = betas[2];
    const u64* __restrict__ H0 = (const u64*)g_h12h[0];
    const u64* __restrict__ H1 = (const u64*)g_h12h[1];
    const u64* __restrict__ H2 = (const u64*)g_h12h[2];
    for (int i = blockIdx.x * blockDim.x + threadIdx.x; i < NN * D / 4;
         i += gridDim.x * blockDim.x) {
        u64 q0 = H0[i], q1 = H1[i], q2 = H2[i];
        float2 a0 = __half22float2(*(__half2*)&q0);
        float2 a1 = __half22float2(*((__half2*)&q0 + 1));
        float2 c0 = __half22float2(*(__half2*)&q1);
        float2 c1 = __half22float2(*((__half2*)&q1 + 1));
        float2 d0 = __half22float2(*(__half2*)&q2);
        float2 d1 = __half22float2(*((__half2*)&q2 + 1));
        float4 v;
        v.x = b0 * a0.x + b1 * c0.x + b2 * d0.x;
        v.y = b0 * a0.y + b1 * c0.y + b2 * d0.y;
        v.z = b0 * a1.x + b1 * c1.x + b2 * d1.x;
        v.w = b0 * a1.y + b1 * c1.y + b2 * d1.y;
        if (l == 0) {
            int j = i * 4;
            float4 x = (j < N_USER * D) ? ((const float4*)uE)[i]
                                        : ((const float4*)iE)[i - N_USER * D / 4];
            float4 f;
            f.x = x.x + v.x; f.y = x.y + v.y; f.z = x.z + v.z; f.w = x.w + v.w;
            ((float4*)g_facc)[i] = f;
            ((float4*)g_X)[i] = v;
        } else {
            float4 f = ((const float4*)g_facc)[i];
            const float k = 1.0f / 3.0f;
            v.x = (f.x + v.x) * k;
            v.y = (f.y + v.y) * k;
            v.z = (f.z + v.z) * k;
            v.w = (f.w + v.w) * k;
            ((float4*)finalOut)[i] = v;
        }
    }
}

// 4 pairs per 256-thread block
__global__ void __launch_bounds__(256) mlp_kernel(
    const int* __restrict__ userIdx, const int* __restrict__ itemIdx,
    const float* __restrict__ W1, const float* __restrict__ b1,
    const float* __restrict__ W2, const float* __restrict__ b2,
    const float* __restrict__ W3, const float* __restrict__ b3,
    const float* __restrict__ finalE,
    float* __restrict__ pred, float* __restrict__ outU, float* __restrict__ outI)
{
    __shared__ float h[4][128];
    __shared__ float h1s[4][64];
    __shared__ float h2s[4][32];
    int g = threadIdx.x >> 6;
    int t = threadIdx.x & 63;
    int bI = blockIdx.x * 4 + g;
    int u = userIdx[bI];
    int v = itemIdx[bI] + N_USER;
    float fu = finalE[(size_t)u * D + t];
    float fi = finalE[(size_t)v * D + t];
    h[g][t] = fu; h[g][64 + t] = fi;
    outU[(size_t)bI * D + t] = fu;
    outI[(size_t)bI * D + t] = fi;
    __syncthreads();

    float acc = b1[t];
    #pragma unroll 16
    for (int k = 0; k < 128; k++) acc += h[g][k] * W1[k * 64 + t];
    h1s[g][t] = fmaxf(acc, 0.f);
    __syncthreads();

    if (t < 32) {
        float a2 = b2[t];
        #pragma unroll 16
        for (int k = 0; k < 64; k++) a2 += h1s[g][k] * W2[k * 32 + t];
        h2s[g][t] = a2;
    }
    __syncthreads();
    if (t < 32) {
        float p = h2s[g][t] * W3[t];
        #pragma unroll
        for (int off = 16; off; off >>= 1) p += __shfl_down_sync(0xffffffffu, p, off);
        if (t == 0) pred[bI] = p + b3[0];
    }
}

// ---------------- launch ----------------
extern "C" void kernel_launch(void* const* d_in, const int* in_sizes, int n_in,
                              void* d_out, int out_size)
{
    const int*   userIdx = (const int*)d_in[0];
    const int*   itemIdx = (const int*)d_in[1];
    const float* uEmbd   = (const float*)d_in[2];
    const float* iEmbd   = (const float*)d_in[3];

    const int*   rowP[3] = { (const int*)d_in[4],  (const int*)d_in[7],  (const int*)d_in[10] };
    const int*   colP[3] = { (const int*)d_in[5],  (const int*)d_in[8],  (const int*)d_in[11] };
    const float* valP[3] = { (const float*)d_in[6], (const float*)d_in[9], (const float*)d_in[12] };

    const float *lin_W, *lin_b, *inter_W, *inter_b;
    const float *attM_W, *attM_b, *attA_W, *attA_b, *attT_W, *attT_b;
    if (in_sizes[14] == 2 * D * D) {
        lin_W   = (const float*)d_in[13];
        inter_W = (const float*)d_in[14];
        attM_W  = (const float*)d_in[15];
        attA_W  = (const float*)d_in[16];
        attT_W  = (const float*)d_in[17];
        lin_b   = (const float*)d_in[18];
        inter_b = (const float*)d_in[19];
        attM_b  = (const float*)d_in[20];
        attA_b  = (const float*)d_in[21];
        attT_b  = (const float*)d_in[22];
    } else {
        lin_W   = (const float*)d_in[13];
        lin_b   = (const float*)d_in[14];
        inter_W = (const float*)d_in[15];
        inter_b = (const float*)d_in[16];
        attM_W  = (const float*)d_in[17];
        attM_b  = (const float*)d_in[18];
        attA_W  = (const float*)d_in[19];
        attA_b  = (const float*)d_in[20];
        attT_W  = (const float*)d_in[21];
        attT_b  = (const float*)d_in[22];
    }
    const float* a_main  = (const float*)d_in[23];
    const float* a_add   = (const float*)d_in[24];
    const float* a_trust = (const float*)d_in[25];
    const float* W1 = (const float*)d_in[26];
    const float* b1 = (const float*)d_in[27];
    const float* W2 = (const float*)d_in[28];
    const float* b2 = (const float*)d_in[29];
    const float* W3 = (const float*)d_in[30];
    const float* b3 = (const float*)d_in[31];

    float* out      = (float*)d_out;
    float* predOut  = out;
    float* userOut  = out + BB;
    float* itemOut  = out + BB + BB * D;
    float* finalOut = out + BB + 2 * BB * D;

    const int TPB = 256;
    const int E4_BLOCKS = (NNZ / 4 + TPB - 1) / TPB;
    const int SPMM_BLOCKS = (NN * 16 + TPB - 1) / TPB;
    const int GEMM_BLOCKS = (NN + 127) / 128;
    const int COMB_BLOCKS = 592;

    const float* iAdj = iEmbd - (size_t)N_USER * D;
    const int THRESH0 = N_USER * D;

    static float* xPtr = nullptr;
    static cudaStream_t st[3];
    static cudaEvent_t evStart, evReady, evL[NLAYERS][3], evC;
    static bool inited = false;
    if (!inited) {
        cudaGetSymbolAddress((void**)&xPtr, g_X);
        for (int r = 0; r < 3; r++) cudaStreamCreateWithFlags(&st[r], cudaStreamNonBlocking);
        cudaEventCreateWithFlags(&evStart, cudaEventDisableTiming);
        cudaEventCreateWithFlags(&evReady, cudaEventDisableTiming);
        cudaEventCreateWithFlags(&evC, cudaEventDisableTiming);
        for (int l = 0; l < NLAYERS; l++)
            for (int r = 0; r < 3; r++)
                cudaEventCreateWithFlags(&evL[l][r], cudaEventDisableTiming);
        cudaFuncSetAttribute(gemm_mma_kernel, cudaFuncAttributeMaxDynamicSharedMemorySize,
                             GEMM_SMEM_BYTES);
        inited = true;
    }

    cudaEventRecord(evStart, 0);
    for (int r = 0; r < 3; r++) {
        cudaStreamWaitEvent(st[r], evStart, 0);
        hist_kernel<<<E4_BLOCKS, TPB, 0, st[r]>>>(rowP[r], r);
        scan_local_kernel<<<NB, 1024, 0, st[r]>>>(r);
        scan_blk_kernel<<<1, 128, 0, st[r]>>>(r);
        scatter_kernel<<<E4_BLOCKS, TPB, 0, st[r]>>>(rowP[r], colP[r], valP[r], r);
        spmm_kernel<<<SPMM_BLOCKS, TPB, 0, st[r]>>>(r, uEmbd, iAdj, THRESH0);
    }

    setup_kernel<<<1, 32>>>();
    wconv_kernel<<<dim3(NLAYERS, 5), 256>>>(lin_W, inter_W, attM_W, attT_W, attA_W);
    cudaEventRecord(evReady, 0);

    for (int r = 0; r < 3; r++) {
        cudaStreamWaitEvent(st[r], evReady, 0);
        gemm_mma_kernel<<<GEMM_BLOCKS, 256, GEMM_SMEM_BYTES, st[r]>>>(
            0, r, lin_b, inter_b, attM_b, attT_b, attA_b, a_main, a_trust, a_add);
        cudaEventRecord(evL[0][r], st[r]);
    }
    for (int r = 0; r < 3; r++) cudaStreamWaitEvent(0, evL[0][r], 0);
    combine_kernel<<<COMB_BLOCKS, 512>>>(0, finalOut, uEmbd, iEmbd);
    cudaEventRecord(evC, 0);

    for (int r = 0; r < 3; r++) {
        cudaStreamWaitEvent(st[r], evC, 0);
        spmm_kernel<<<SPMM_BLOCKS, TPB, 0, st[r]>>>(r, xPtr, xPtr, 0x7fffffff);
        gemm_mma_kernel<<<GEMM_BLOCKS, 256, GEMM_SMEM_BYTES, st[r]>>>(
            1, r, lin_b, inter_b, attM_b, attT_b, attA_b, a_main, a_trust, a_add);
        cudaEventRecord(evL[1][r], st[r]);
    }
    for (int r = 0; r < 3; r++) cudaStreamWaitEvent(0, evL[1][r], 0);
    combine_kernel<<<COMB_BLOCKS, 512>>>(1, finalOut, uEmbd, iEmbd);

    mlp_kernel<<<BB / 4, 256>>>(userIdx, itemIdx, W1, b1, W2, b2, W3, b3,
                                finalOut, predOut, userOut, itemOut);
}